// round 1
// baseline (speedup 1.0000x reference)
#include <cuda_runtime.h>

// Problem constants
// x: [2, 2048, 1024]  Q,K: [16, 64, 1024]  VO: [16, 1024, 1024]
// out: [2, 2048, 1024]
#define BDIM   1024
#define BRANK  64
#define BHEADS 16
#define BB     2
#define BT     2048

// Scratch (device globals: allocation-free per harness rules)
__device__ float g_xq[(size_t)BB * BT * BHEADS * BRANK];            // 16 MB  [bt, h*R+r]
__device__ float g_xk[(size_t)BB * BT * BHEADS * BRANK];            // 16 MB
__device__ float g_scores[(size_t)BB * BHEADS * BT * BT];           // 537 MB [b,h,t,u]
__device__ float g_ctx[(size_t)BB * BT * BHEADS * BDIM];            // 256 MB [bt, h*D+d]

#define GBM 128
#define GBN 128
#define GBK 8

// C[M,N] = alpha * A[M,K] @ op(B),  A row-major (lda), C row-major (ldc)
// NT=true : B is [N,K] row-major (ldb over N rows)
// NT=false: B is [K,N] row-major (ldb over K rows)
// Batch via blockIdx.z: z -> (zo, zi) with zi = z % innerCount; per-batch base offsets.
template <bool NT>
__global__ __launch_bounds__(256)
void gemm_f32(const float* __restrict__ Abase, const float* __restrict__ Bbase,
              float* __restrict__ Cbase,
              int M, int N, int K,
              int lda, int ldb, int ldc,
              long long oAo, long long oAi,
              long long oBo, long long oBi,
              long long oCo, long long oCi,
              int innerCount, float alpha)
{
    const int z  = blockIdx.z;
    const int zo = z / innerCount;
    const int zi = z - zo * innerCount;
    const float* A = Abase + zo * oAo + zi * oAi;
    const float* Bp = Bbase + zo * oBo + zi * oBi;
    float* C = Cbase + zo * oCo + zi * oCi;

    __shared__ float As[GBK][GBM];
    __shared__ float Bs[GBK][GBN + 4];

    const int tid = threadIdx.x;           // 256 threads
    const int tr = tid >> 4;               // 0..15
    const int tc = tid & 15;               // 0..15
    const int row0 = blockIdx.y * GBM;
    const int col0 = blockIdx.x * GBN;

    float acc[8][8];
#pragma unroll
    for (int i = 0; i < 8; i++)
#pragma unroll
        for (int j = 0; j < 8; j++) acc[i][j] = 0.0f;

    // A tile load mapping: 128 rows x 8 cols; one float4 per thread
    const int arow = tid >> 1;
    const int acol = (tid & 1) * 4;
    // B tile load mapping
    int brow, bcol;
    if (NT) { brow = tid >> 1; bcol = (tid & 1) * 4; }   // [BN=128 rows, BK=8 cols]
    else    { brow = tid >> 5; bcol = (tid & 31) * 4; }  // [BK=8 rows, BN=128 cols]

    for (int k0 = 0; k0 < K; k0 += GBK) {
        // Load A tile (coalesced along K), store transposed
        {
            float4 av = *reinterpret_cast<const float4*>(
                A + (long long)(row0 + arow) * lda + (k0 + acol));
            As[acol + 0][arow] = av.x;
            As[acol + 1][arow] = av.y;
            As[acol + 2][arow] = av.z;
            As[acol + 3][arow] = av.w;
        }
        // Load B tile
        if (NT) {
            float4 bv = *reinterpret_cast<const float4*>(
                Bp + (long long)(col0 + brow) * ldb + (k0 + bcol));
            Bs[bcol + 0][brow] = bv.x;
            Bs[bcol + 1][brow] = bv.y;
            Bs[bcol + 2][brow] = bv.z;
            Bs[bcol + 3][brow] = bv.w;
        } else {
            float4 bv = *reinterpret_cast<const float4*>(
                Bp + (long long)(k0 + brow) * ldb + (col0 + bcol));
            *reinterpret_cast<float4*>(&Bs[brow][bcol]) = bv;
        }
        __syncthreads();

#pragma unroll
        for (int kk = 0; kk < GBK; kk++) {
            float4 a0 = *reinterpret_cast<const float4*>(&As[kk][tr * 8]);
            float4 a1 = *reinterpret_cast<const float4*>(&As[kk][tr * 8 + 4]);
            float4 b0 = *reinterpret_cast<const float4*>(&Bs[kk][tc * 8]);
            float4 b1 = *reinterpret_cast<const float4*>(&Bs[kk][tc * 8 + 4]);
            float ar[8] = {a0.x, a0.y, a0.z, a0.w, a1.x, a1.y, a1.z, a1.w};
            float br[8] = {b0.x, b0.y, b0.z, b0.w, b1.x, b1.y, b1.z, b1.w};
#pragma unroll
            for (int i = 0; i < 8; i++)
#pragma unroll
                for (int j = 0; j < 8; j++)
                    acc[i][j] += ar[i] * br[j];
        }
        __syncthreads();
    }

#pragma unroll
    for (int i = 0; i < 8; i++) {
        const long long crow = (long long)(row0 + tr * 8 + i) * ldc + col0 + tc * 8;
#pragma unroll
        for (int j = 0; j < 8; j += 4) {
            float4 v;
            v.x = acc[i][j + 0] * alpha;
            v.y = acc[i][j + 1] * alpha;
            v.z = acc[i][j + 2] * alpha;
            v.w = acc[i][j + 3] * alpha;
            *reinterpret_cast<float4*>(C + crow + j) = v;
        }
    }
}

// Row softmax over rows of length 2048. One block (256 thr) per row.
__global__ __launch_bounds__(256)
void softmax_rows(float* __restrict__ S)
{
    const long long row = blockIdx.x;
    float* p = S + row * (long long)BT;
    const int tid = threadIdx.x;

    float v[8];
    float m = -1e30f;
#pragma unroll
    for (int i = 0; i < 8; i++) {
        v[i] = p[tid + i * 256];
        m = fmaxf(m, v[i]);
    }
    __shared__ float red[256];
    red[tid] = m;
    __syncthreads();
    for (int s = 128; s > 0; s >>= 1) {
        if (tid < s) red[tid] = fmaxf(red[tid], red[tid + s]);
        __syncthreads();
    }
    m = red[0];
    __syncthreads();

    float sum = 0.0f;
#pragma unroll
    for (int i = 0; i < 8; i++) {
        v[i] = __expf(v[i] - m);
        sum += v[i];
    }
    red[tid] = sum;
    __syncthreads();
    for (int s = 128; s > 0; s >>= 1) {
        if (tid < s) red[tid] += red[tid + s];
        __syncthreads();
    }
    const float inv = 1.0f / red[0];
#pragma unroll
    for (int i = 0; i < 8; i++) p[tid + i * 256] = v[i] * inv;
}

extern "C" void kernel_launch(void* const* d_in, const int* in_sizes, int n_in,
                              void* d_out, int out_size)
{
    const float* x  = (const float*)d_in[0];   // [2,2048,1024]
    const float* Q  = (const float*)d_in[1];   // [16,64,1024] -> flat [1024,1024]
    const float* K  = (const float*)d_in[2];
    const float* VO = (const float*)d_in[3];   // [16,1024,1024] -> flat [16384,1024]
    float* out = (float*)d_out;                // [2,2048,1024]

    float *xq, *xk, *sc, *ctx;
    cudaGetSymbolAddress((void**)&xq,  g_xq);
    cudaGetSymbolAddress((void**)&xk,  g_xk);
    cudaGetSymbolAddress((void**)&sc,  g_scores);
    cudaGetSymbolAddress((void**)&ctx, g_ctx);

    const dim3 blk(256);
    const int MBT = BB * BT;                  // 4096
    const int HR  = BHEADS * BRANK;           // 1024
    const int HD  = BHEADS * BDIM;            // 16384

    // 1) xq = x @ Q^T   [4096,1024] = [4096,1024] @ [1024,1024]^T
    gemm_f32<true><<<dim3(HR / GBN, MBT / GBM, 1), blk>>>(
        x, Q, xq, MBT, HR, BDIM, BDIM, BDIM, HR,
        0, 0, 0, 0, 0, 0, 1, 1.0f);
    // 2) xk = x @ K^T
    gemm_f32<true><<<dim3(HR / GBN, MBT / GBM, 1), blk>>>(
        x, K, xk, MBT, HR, BDIM, BDIM, BDIM, HR,
        0, 0, 0, 0, 0, 0, 1, 1.0f);

    // 3) scores[b,h] = xq_bh @ xk_bh^T / 32   per (b,h): [2048,2048,K=64]
    gemm_f32<true><<<dim3(BT / GBN, BT / GBM, BB * BHEADS), blk>>>(
        xq, xk, sc, BT, BT, BRANK, HR, HR, BT,
        (long long)BT * HR, (long long)BRANK,
        (long long)BT * HR, (long long)BRANK,
        (long long)BHEADS * BT * BT, (long long)BT * BT,
        BHEADS, 0.03125f);

    // 4) softmax over u
    softmax_rows<<<BB * BHEADS * BT, blk>>>(sc);

    // 5) ctx[b,h] = P_bh @ x_b   per (b,h): [2048,1024,K=2048] -> ctx[bt, h*D+d]
    gemm_f32<false><<<dim3(BDIM / GBN, BT / GBM, BB * BHEADS), blk>>>(
        sc, x, ctx, BT, BDIM, BT, BT, BDIM, HD,
        (long long)BHEADS * BT * BT, (long long)BT * BT,
        (long long)BT * BDIM, 0,
        (long long)BT * HD, (long long)BDIM,
        BHEADS, 1.0f);

    // 6) out = ctx @ VO_flat   [4096,1024] = [4096,16384] @ [16384,1024]
    gemm_f32<false><<<dim3(BDIM / GBN, MBT / GBM, 1), blk>>>(
        ctx, VO, out, MBT, BDIM, HD, HD, BDIM, BDIM,
        0, 0, 0, 0, 0, 0, 1, 1.0f);
}

// round 3
// speedup vs baseline: 2.5844x; 2.5844x over previous
#include <cuda_runtime.h>
#include <cuda_bf16.h>
#include <cstdint>

// Problem constants
#define BDIM   1024
#define BRANK  64
#define BHEADS 16
#define BB     2
#define BT     2048

// ---------------------------------------------------------------------------
// Scratch (device globals: allocation-free per harness rules)
// ---------------------------------------------------------------------------
__device__ __align__(256) float g_xq[(size_t)BB * BT * BHEADS * BRANK];   // 16 MB
__device__ __align__(256) float g_xk[(size_t)BB * BT * BHEADS * BRANK];   // 16 MB
__device__ __align__(256) float g_scores[(size_t)BB * BHEADS * BT * BT];  // 537 MB
__device__ __align__(256) __nv_bfloat16 g_phi[(size_t)BB * BHEADS * BT * BT];
__device__ __align__(256) __nv_bfloat16 g_plo[(size_t)BB * BHEADS * BT * BT];
__device__ __align__(256) __nv_bfloat16 g_xthi[(size_t)BB * BDIM * BT];
__device__ __align__(256) __nv_bfloat16 g_xtlo[(size_t)BB * BDIM * BT];
__device__ __align__(256) __nv_bfloat16 g_ctxhi[(size_t)BB * BT * BHEADS * BDIM];
__device__ __align__(256) __nv_bfloat16 g_ctxlo[(size_t)BB * BT * BHEADS * BDIM];
__device__ __align__(256) __nv_bfloat16 g_vothi[(size_t)BDIM * BHEADS * BDIM];
__device__ __align__(256) __nv_bfloat16 g_votlo[(size_t)BDIM * BHEADS * BDIM];

// ---------------------------------------------------------------------------
// Helpers
// ---------------------------------------------------------------------------
__device__ __forceinline__ uint32_t smem_u32(const void* p) {
    return (uint32_t)__cvta_generic_to_shared(p);
}

#define CP16(s, g) asm volatile("cp.async.cg.shared.global [%0], [%1], 16;" :: "r"(s), "l"(g))

__device__ __forceinline__ void ldsm4(uint32_t* r, uint32_t addr) {
    asm volatile("ldmatrix.sync.aligned.m8n8.x4.shared.b16 {%0,%1,%2,%3}, [%4];"
        : "=r"(r[0]), "=r"(r[1]), "=r"(r[2]), "=r"(r[3]) : "r"(addr));
}

__device__ __forceinline__ void mma16816(float* c, const uint32_t* a, const uint32_t* b) {
    asm volatile("mma.sync.aligned.m16n8k16.row.col.f32.bf16.bf16.f32 "
        "{%0,%1,%2,%3}, {%4,%5,%6,%7}, {%8,%9}, {%0,%1,%2,%3};"
        : "+f"(c[0]), "+f"(c[1]), "+f"(c[2]), "+f"(c[3])
        : "r"(a[0]), "r"(a[1]), "r"(a[2]), "r"(a[3]), "r"(b[0]), "r"(b[1]));
}

// ---------------------------------------------------------------------------
// fp32 tiled GEMM (stages 1-3)
// ---------------------------------------------------------------------------
#define GBM 128
#define GBN 128
#define GBK 8

template <bool NT>
__global__ __launch_bounds__(256)
void gemm_f32(const float* __restrict__ Abase, const float* __restrict__ Bbase,
              float* __restrict__ Cbase,
              int M, int N, int K,
              int lda, int ldb, int ldc,
              long long oAo, long long oAi,
              long long oBo, long long oBi,
              long long oCo, long long oCi,
              int innerCount, float alpha)
{
    const int z  = blockIdx.z;
    const int zo = z / innerCount;
    const int zi = z - zo * innerCount;
    const float* A = Abase + zo * oAo + zi * oAi;
    const float* Bp = Bbase + zo * oBo + zi * oBi;
    float* C = Cbase + zo * oCo + zi * oCi;

    __shared__ float As[GBK][GBM];
    __shared__ float Bs[GBK][GBN + 4];

    const int tid = threadIdx.x;
    const int tr = tid >> 4;
    const int tc = tid & 15;
    const int row0 = blockIdx.y * GBM;
    const int col0 = blockIdx.x * GBN;

    float acc[8][8];
#pragma unroll
    for (int i = 0; i < 8; i++)
#pragma unroll
        for (int j = 0; j < 8; j++) acc[i][j] = 0.0f;

    const int arow = tid >> 1;
    const int acol = (tid & 1) * 4;
    int brow, bcol;
    if (NT) { brow = tid >> 1; bcol = (tid & 1) * 4; }
    else    { brow = tid >> 5; bcol = (tid & 31) * 4; }

    for (int k0 = 0; k0 < K; k0 += GBK) {
        {
            float4 av = *reinterpret_cast<const float4*>(
                A + (long long)(row0 + arow) * lda + (k0 + acol));
            As[acol + 0][arow] = av.x;
            As[acol + 1][arow] = av.y;
            As[acol + 2][arow] = av.z;
            As[acol + 3][arow] = av.w;
        }
        if (NT) {
            float4 bv = *reinterpret_cast<const float4*>(
                Bp + (long long)(col0 + brow) * ldb + (k0 + bcol));
            Bs[bcol + 0][brow] = bv.x;
            Bs[bcol + 1][brow] = bv.y;
            Bs[bcol + 2][brow] = bv.z;
            Bs[bcol + 3][brow] = bv.w;
        } else {
            float4 bv = *reinterpret_cast<const float4*>(
                Bp + (long long)(k0 + brow) * ldb + (col0 + bcol));
            *reinterpret_cast<float4*>(&Bs[brow][bcol]) = bv;
        }
        __syncthreads();

#pragma unroll
        for (int kk = 0; kk < GBK; kk++) {
            float4 a0 = *reinterpret_cast<const float4*>(&As[kk][tr * 8]);
            float4 a1 = *reinterpret_cast<const float4*>(&As[kk][tr * 8 + 4]);
            float4 b0 = *reinterpret_cast<const float4*>(&Bs[kk][tc * 8]);
            float4 b1 = *reinterpret_cast<const float4*>(&Bs[kk][tc * 8 + 4]);
            float ar[8] = {a0.x, a0.y, a0.z, a0.w, a1.x, a1.y, a1.z, a1.w};
            float br[8] = {b0.x, b0.y, b0.z, b0.w, b1.x, b1.y, b1.z, b1.w};
#pragma unroll
            for (int i = 0; i < 8; i++)
#pragma unroll
                for (int j = 0; j < 8; j++)
                    acc[i][j] += ar[i] * br[j];
        }
        __syncthreads();
    }

#pragma unroll
    for (int i = 0; i < 8; i++) {
        const long long crow = (long long)(row0 + tr * 8 + i) * ldc + col0 + tc * 8;
#pragma unroll
        for (int j = 0; j < 8; j += 4) {
            float4 v;
            v.x = acc[i][j + 0] * alpha;
            v.y = acc[i][j + 1] * alpha;
            v.z = acc[i][j + 2] * alpha;
            v.w = acc[i][j + 3] * alpha;
            *reinterpret_cast<float4*>(C + crow + j) = v;
        }
    }
}

// ---------------------------------------------------------------------------
// Softmax over rows of 2048 -> bf16 hi/lo split probabilities
// ---------------------------------------------------------------------------
__global__ __launch_bounds__(256)
void softmax_split(const float* __restrict__ S,
                   __nv_bfloat16* __restrict__ PH, __nv_bfloat16* __restrict__ PL)
{
    const long long row = blockIdx.x;
    const float* p = S + row * (long long)BT;
    const int tid = threadIdx.x;

    float v[8];
    float m = -1e30f;
#pragma unroll
    for (int i = 0; i < 8; i++) {
        v[i] = p[tid + i * 256];
        m = fmaxf(m, v[i]);
    }
    __shared__ float red[256];
    red[tid] = m;
    __syncthreads();
    for (int s = 128; s > 0; s >>= 1) {
        if (tid < s) red[tid] = fmaxf(red[tid], red[tid + s]);
        __syncthreads();
    }
    m = red[0];
    __syncthreads();

    float sum = 0.0f;
#pragma unroll
    for (int i = 0; i < 8; i++) {
        v[i] = __expf(v[i] - m);
        sum += v[i];
    }
    red[tid] = sum;
    __syncthreads();
    for (int s = 128; s > 0; s >>= 1) {
        if (tid < s) red[tid] += red[tid + s];
        __syncthreads();
    }
    const float inv = 1.0f / red[0];
    __nv_bfloat16* ph = PH + row * (long long)BT;
    __nv_bfloat16* pl = PL + row * (long long)BT;
#pragma unroll
    for (int i = 0; i < 8; i++) {
        float pv = v[i] * inv;
        __nv_bfloat16 h = __float2bfloat16(pv);
        float lo = pv - __bfloat162float(h);
        ph[tid + i * 256] = h;
        pl[tid + i * 256] = __float2bfloat16(lo);
    }
}

// ---------------------------------------------------------------------------
// Transpose + hi/lo split: out[c][r] (hi,lo bf16) = in[r][c] (fp32), batched
// ---------------------------------------------------------------------------
__global__ __launch_bounds__(256)
void transpose_split(const float* __restrict__ in, long long inBS, int R, int C,
                     __nv_bfloat16* __restrict__ oh, __nv_bfloat16* __restrict__ ol,
                     int oLd, long long oBS)
{
    __shared__ float tile[32][33];
    const int z = blockIdx.z;
    const float* ip = in + (long long)z * inBS;
    const int c0 = blockIdx.x * 32;
    const int r0 = blockIdx.y * 32;
    const int tx = threadIdx.x;
    const int ty = threadIdx.y;

#pragma unroll
    for (int i = 0; i < 32; i += 8)
        tile[ty + i][tx] = ip[(long long)(r0 + ty + i) * C + c0 + tx];
    __syncthreads();

    const long long ob = (long long)z * oBS;
#pragma unroll
    for (int i = 0; i < 32; i += 8) {
        float v = tile[tx][ty + i];
        __nv_bfloat16 h = __float2bfloat16(v);
        float lo = v - __bfloat162float(h);
        long long o = ob + (long long)(c0 + ty + i) * oLd + r0 + tx;
        oh[o] = h;
        ol[o] = __float2bfloat16(lo);
    }
}

// ---------------------------------------------------------------------------
// HMMA bf16-split GEMM: C[128x128 tile] = (Ahi+Alo) @ (Bhi+Blo)^T
// A: [M][K] K-major rows. B (pre-transposed): [N][K] K-major rows.
// 3 terms: hi*hi + hi*lo + lo*hi, fp32 accumulate in registers.
// STAGE==4: A=P rows (b,h,t flat), B=xT per batch; epilogue -> ctx hi/lo bf16.
// STAGE==5: A=ctx hi/lo, B=VOT; epilogue -> fp32 out.
// ---------------------------------------------------------------------------
#define HTM 128
#define HTN 128
#define HTK 64

#define BUFSTRIDE 65536          // 4 tiles x 16KB
#define AHI_O 0
#define ALO_O 16384
#define BHI_O 32768
#define BLO_O 49152
#define HMMA_SMEM (2 * BUFSTRIDE)   // 128 KB

template <int STAGE>
__global__ __launch_bounds__(256, 1)
void hmma_gemm(const __nv_bfloat16* __restrict__ Ahi, const __nv_bfloat16* __restrict__ Alo,
               const __nv_bfloat16* __restrict__ Bhi, const __nv_bfloat16* __restrict__ Blo,
               float* __restrict__ Cf,
               __nv_bfloat16* __restrict__ Chi, __nv_bfloat16* __restrict__ Clo,
               int K)
{
    extern __shared__ char smem[];
    const uint32_t sb = smem_u32(smem);
    const int tid  = threadIdx.x;
    const int wid  = tid >> 5;
    const int lane = tid & 31;
    const int mw = wid & 3;    // 4 M-warps (32 rows each)
    const int nw = wid >> 2;   // 2 N-warps (64 cols each)

    const long long m0 = (long long)blockIdx.y * HTM;
    const int n0 = blockIdx.x * HTN;

    const __nv_bfloat16* Abh = Ahi + m0 * K;
    const __nv_bfloat16* Abl = Alo + m0 * K;
    const __nv_bfloat16* Bbh;
    const __nv_bfloat16* Bbl;
    if (STAGE == 4) {
        const long long b = m0 >> 15;    // 32768 flat rows per batch
        Bbh = Bhi + b * ((long long)BDIM * BT) + (long long)n0 * K;
        Bbl = Blo + b * ((long long)BDIM * BT) + (long long)n0 * K;
    } else {
        Bbh = Bhi + (long long)n0 * K;
        Bbl = Blo + (long long)n0 * K;
    }

    float acc[2][8][4];
#pragma unroll
    for (int i = 0; i < 2; i++)
#pragma unroll
        for (int f = 0; f < 8; f++)
#pragma unroll
            for (int e = 0; e < 4; e++) acc[i][f][e] = 0.0f;

    const int NC = K / HTK;

    // chunk loader: 128 rows x 8 x 16B per tile, SW128 swizzle, 4 tiles
    auto load_chunk = [&](int c, int buf) {
        const long long kg = (long long)c * HTK;
        const uint32_t bb = sb + buf * BUFSTRIDE;
#pragma unroll
        for (int i = 0; i < 4; i++) {
            const int idx = tid + i * 256;
            const int r  = idx >> 3;
            const int ck = idx & 7;
            const uint32_t so = (uint32_t)(r * 128 + ((ck ^ (r & 7)) << 4));
            const long long go = (long long)r * K + kg + ck * 8;
            CP16(bb + AHI_O + so, (const void*)(Abh + go));
            CP16(bb + ALO_O + so, (const void*)(Abl + go));
            CP16(bb + BHI_O + so, (const void*)(Bbh + go));
            CP16(bb + BLO_O + so, (const void*)(Bbl + go));
        }
        asm volatile("cp.async.commit_group;" ::: "memory");
    };

    load_chunk(0, 0);
    load_chunk(1, 1);

    for (int c = 0; c < NC; c++) {
        asm volatile("cp.async.wait_group 1;" ::: "memory");
        __syncthreads();

        const uint32_t ab = sb + (c & 1) * BUFSTRIDE;
#pragma unroll
        for (int ks = 0; ks < 4; ks++) {
            uint32_t ah[2][4], al[2][4], bh[4][4], bl[4][4];
#pragma unroll
            for (int i = 0; i < 2; i++) {
                const int r  = mw * 32 + i * 16 + (lane & 15);
                const int ck = ks * 2 + (lane >> 4);
                const uint32_t off = (uint32_t)(r * 128 + ((ck ^ (r & 7)) << 4));
                ldsm4(ah[i], ab + AHI_O + off);
                ldsm4(al[i], ab + ALO_O + off);
            }
#pragma unroll
            for (int j = 0; j < 4; j++) {
                const int r  = nw * 64 + j * 16 + (lane & 7) + ((lane >> 4) & 1) * 8;
                const int ck = ks * 2 + ((lane >> 3) & 1);
                const uint32_t off = (uint32_t)(r * 128 + ((ck ^ (r & 7)) << 4));
                ldsm4(bh[j], ab + BHI_O + off);
                ldsm4(bl[j], ab + BLO_O + off);
            }
#pragma unroll
            for (int i = 0; i < 2; i++)
#pragma unroll
                for (int f = 0; f < 8; f++) {
                    const uint32_t* Bh = &bh[f >> 1][(f & 1) * 2];
                    const uint32_t* Bl = &bl[f >> 1][(f & 1) * 2];
                    mma16816(acc[i][f], ah[i], Bh);
                    mma16816(acc[i][f], ah[i], Bl);
                    mma16816(acc[i][f], al[i], Bh);
                }
        }
        __syncthreads();
        if (c + 2 < NC) load_chunk(c + 2, c & 1);
    }

    // Epilogue
#pragma unroll
    for (int i = 0; i < 2; i++) {
#pragma unroll
        for (int hr = 0; hr < 2; hr++) {
            const long long mg = m0 + mw * 32 + i * 16 + hr * 8 + (lane >> 2);
            const int ncol = n0 + nw * 64 + (lane & 3) * 2;
            if (STAGE == 5) {
                float* dst = Cf + mg * BDIM + ncol;
#pragma unroll
                for (int f = 0; f < 8; f++) {
                    float2 v;
                    v.x = acc[i][f][hr * 2 + 0];
                    v.y = acc[i][f][hr * 2 + 1];
                    *reinterpret_cast<float2*>(dst + f * 8) = v;
                }
            } else {
                const int b = (int)(mg >> 15);
                const int h = (int)((mg >> 11) & 15);
                const int t = (int)(mg & 2047);
                const long long orow =
                    ((long long)b * BT + t) * ((long long)BHEADS * BDIM) +
                    (long long)h * BDIM + ncol;
#pragma unroll
                for (int f = 0; f < 8; f++) {
                    const float v0 = acc[i][f][hr * 2 + 0];
                    const float v1 = acc[i][f][hr * 2 + 1];
                    __nv_bfloat162 hv, lv;
                    hv.x = __float2bfloat16(v0);
                    hv.y = __float2bfloat16(v1);
                    lv.x = __float2bfloat16(v0 - __bfloat162float(hv.x));
                    lv.y = __float2bfloat16(v1 - __bfloat162float(hv.y));
                    *reinterpret_cast<__nv_bfloat162*>(Chi + orow + f * 8) = hv;
                    *reinterpret_cast<__nv_bfloat162*>(Clo + orow + f * 8) = lv;
                }
            }
        }
    }
}

// ---------------------------------------------------------------------------
// Launch
// ---------------------------------------------------------------------------
extern "C" void kernel_launch(void* const* d_in, const int* in_sizes, int n_in,
                              void* d_out, int out_size)
{
    const float* x  = (const float*)d_in[0];   // [2,2048,1024]
    const float* Q  = (const float*)d_in[1];   // [16,64,1024]
    const float* K  = (const float*)d_in[2];
    const float* VO = (const float*)d_in[3];   // [16,1024,1024]
    float* out = (float*)d_out;                // [2,2048,1024]

    float *xq, *xk, *sc;
    __nv_bfloat16 *phi, *plo, *xthi, *xtlo, *ctxhi, *ctxlo, *vothi, *votlo;
    cudaGetSymbolAddress((void**)&xq,    g_xq);
    cudaGetSymbolAddress((void**)&xk,    g_xk);
    cudaGetSymbolAddress((void**)&sc,    g_scores);
    cudaGetSymbolAddress((void**)&phi,   g_phi);
    cudaGetSymbolAddress((void**)&plo,   g_plo);
    cudaGetSymbolAddress((void**)&xthi,  g_xthi);
    cudaGetSymbolAddress((void**)&xtlo,  g_xtlo);
    cudaGetSymbolAddress((void**)&ctxhi, g_ctxhi);
    cudaGetSymbolAddress((void**)&ctxlo, g_ctxlo);
    cudaGetSymbolAddress((void**)&vothi, g_vothi);
    cudaGetSymbolAddress((void**)&votlo, g_votlo);

    cudaFuncSetAttribute(hmma_gemm<4>, cudaFuncAttributeMaxDynamicSharedMemorySize, HMMA_SMEM);
    cudaFuncSetAttribute(hmma_gemm<5>, cudaFuncAttributeMaxDynamicSharedMemorySize, HMMA_SMEM);

    const dim3 blk(256);
    const int MBT = BB * BT;                  // 4096
    const int HR  = BHEADS * BRANK;           // 1024
    const int HD  = BHEADS * BDIM;            // 16384

    // Transposed/split operands (independent of stages 1-3)
    transpose_split<<<dim3(BDIM / 32, BT / 32, BB), dim3(32, 8)>>>(
        x, (long long)BT * BDIM, BT, BDIM, xthi, xtlo, BT, (long long)BDIM * BT);
    transpose_split<<<dim3(BDIM / 32, BDIM / 32, BHEADS), dim3(32, 8)>>>(
        VO, (long long)BDIM * BDIM, BDIM, BDIM, vothi, votlo, HD, (long long)BDIM);

    // 1) xq = x @ Q^T
    gemm_f32<true><<<dim3(HR / GBN, MBT / GBM, 1), blk>>>(
        x, Q, xq, MBT, HR, BDIM, BDIM, BDIM, HR,
        0, 0, 0, 0, 0, 0, 1, 1.0f);
    // 2) xk = x @ K^T
    gemm_f32<true><<<dim3(HR / GBN, MBT / GBM, 1), blk>>>(
        x, K, xk, MBT, HR, BDIM, BDIM, BDIM, HR,
        0, 0, 0, 0, 0, 0, 1, 1.0f);
    // 3) scores = xq @ xk^T / 32 per (b,h)
    gemm_f32<true><<<dim3(BT / GBN, BT / GBM, BB * BHEADS), blk>>>(
        xq, xk, sc, BT, BT, BRANK, HR, HR, BT,
        (long long)BT * HR, (long long)BRANK,
        (long long)BT * HR, (long long)BRANK,
        (long long)BHEADS * BT * BT, (long long)BT * BT,
        BHEADS, 0.03125f);
    // 4) softmax -> P hi/lo
    softmax_split<<<BB * BHEADS * BT, blk>>>(sc, phi, plo);

    // 5) ctx = P @ x  (HMMA bf16-split)  M=65536 flat (b,h,t), N=1024, K=2048
    hmma_gemm<4><<<dim3(BDIM / HTN, (BB * BHEADS * BT) / HTM), 256, HMMA_SMEM>>>(
        phi, plo, xthi, xtlo, nullptr, ctxhi, ctxlo, BT);

    // 6) out = ctx @ VO  (HMMA bf16-split)  M=4096, N=1024, K=16384
    hmma_gemm<5><<<dim3(BDIM / HTN, MBT / HTM), 256, HMMA_SMEM>>>(
        ctxhi, ctxlo, vothi, votlo, out, nullptr, nullptr, HD);
}

// round 4
// speedup vs baseline: 2.9841x; 1.1547x over previous
#include <cuda_runtime.h>
#include <cuda_bf16.h>
#include <cstdint>

// Problem constants
#define BDIM   1024
#define BRANK  64
#define BHEADS 16
#define BB     2
#define BT     2048

// ---------------------------------------------------------------------------
// Scratch (device globals)
// ---------------------------------------------------------------------------
__device__ __align__(256) float g_scores[(size_t)BB * BHEADS * BT * BT];  // 537 MB
__device__ __align__(256) __nv_bfloat16 g_phi[(size_t)BB * BHEADS * BT * BT];
__device__ __align__(256) __nv_bfloat16 g_plo[(size_t)BB * BHEADS * BT * BT];
// row-major splits of inputs
__device__ __align__(256) __nv_bfloat16 g_xhi[(size_t)BB * BT * BDIM];
__device__ __align__(256) __nv_bfloat16 g_xlo[(size_t)BB * BT * BDIM];
__device__ __align__(256) __nv_bfloat16 g_qhi[(size_t)BHEADS * BRANK * BDIM];
__device__ __align__(256) __nv_bfloat16 g_qlo[(size_t)BHEADS * BRANK * BDIM];
__device__ __align__(256) __nv_bfloat16 g_khi[(size_t)BHEADS * BRANK * BDIM];
__device__ __align__(256) __nv_bfloat16 g_klo[(size_t)BHEADS * BRANK * BDIM];
// projections (split, written by HMMA epilogue)
__device__ __align__(256) __nv_bfloat16 g_xqhi[(size_t)BB * BT * BHEADS * BRANK];
__device__ __align__(256) __nv_bfloat16 g_xqlo[(size_t)BB * BT * BHEADS * BRANK];
__device__ __align__(256) __nv_bfloat16 g_xkhi[(size_t)BB * BT * BHEADS * BRANK];
__device__ __align__(256) __nv_bfloat16 g_xklo[(size_t)BB * BT * BHEADS * BRANK];
// x transposed per batch: [b][d][u]
__device__ __align__(256) __nv_bfloat16 g_xthi[(size_t)BB * BDIM * BT];
__device__ __align__(256) __nv_bfloat16 g_xtlo[(size_t)BB * BDIM * BT];
// ctx split: [bt][h*D+d]
__device__ __align__(256) __nv_bfloat16 g_ctxhi[(size_t)BB * BT * BHEADS * BDIM];
__device__ __align__(256) __nv_bfloat16 g_ctxlo[(size_t)BB * BT * BHEADS * BDIM];
// VO transposed: [e][h*D+d]
__device__ __align__(256) __nv_bfloat16 g_vothi[(size_t)BDIM * BHEADS * BDIM];
__device__ __align__(256) __nv_bfloat16 g_votlo[(size_t)BDIM * BHEADS * BDIM];

// ---------------------------------------------------------------------------
// Helpers
// ---------------------------------------------------------------------------
__device__ __forceinline__ uint32_t smem_u32(const void* p) {
    return (uint32_t)__cvta_generic_to_shared(p);
}

#define CP16(s, g) asm volatile("cp.async.cg.shared.global [%0], [%1], 16;" :: "r"(s), "l"(g))

__device__ __forceinline__ void ldsm4(uint32_t* r, uint32_t addr) {
    asm volatile("ldmatrix.sync.aligned.m8n8.x4.shared.b16 {%0,%1,%2,%3}, [%4];"
        : "=r"(r[0]), "=r"(r[1]), "=r"(r[2]), "=r"(r[3]) : "r"(addr));
}

__device__ __forceinline__ void mma16816(float* c, const uint32_t* a, const uint32_t* b) {
    asm volatile("mma.sync.aligned.m16n8k16.row.col.f32.bf16.bf16.f32 "
        "{%0,%1,%2,%3}, {%4,%5,%6,%7}, {%8,%9}, {%0,%1,%2,%3};"
        : "+f"(c[0]), "+f"(c[1]), "+f"(c[2]), "+f"(c[3])
        : "r"(a[0]), "r"(a[1]), "r"(a[2]), "r"(a[3]), "r"(b[0]), "r"(b[1]));
}

template <int N>
__device__ __forceinline__ void cp_wait() {
    asm volatile("cp.async.wait_group %0;" :: "n"(N) : "memory");
}

// ---------------------------------------------------------------------------
// Elementwise hi/lo split: fp32 -> bf16 hi + bf16 lo (float4 per thread)
// ---------------------------------------------------------------------------
__global__ __launch_bounds__(256)
void split_f32(const float* __restrict__ in,
               __nv_bfloat16* __restrict__ oh, __nv_bfloat16* __restrict__ ol,
               long long n4)
{
    const long long i = (long long)blockIdx.x * 256 + threadIdx.x;
    if (i >= n4) return;
    float4 v = reinterpret_cast<const float4*>(in)[i];
    __nv_bfloat162 h01, h23, l01, l23;
    h01.x = __float2bfloat16(v.x); h01.y = __float2bfloat16(v.y);
    h23.x = __float2bfloat16(v.z); h23.y = __float2bfloat16(v.w);
    l01.x = __float2bfloat16(v.x - __bfloat162float(h01.x));
    l01.y = __float2bfloat16(v.y - __bfloat162float(h01.y));
    l23.x = __float2bfloat16(v.z - __bfloat162float(h23.x));
    l23.y = __float2bfloat16(v.w - __bfloat162float(h23.y));
    reinterpret_cast<__nv_bfloat162*>(oh)[2 * i + 0] = h01;
    reinterpret_cast<__nv_bfloat162*>(oh)[2 * i + 1] = h23;
    reinterpret_cast<__nv_bfloat162*>(ol)[2 * i + 0] = l01;
    reinterpret_cast<__nv_bfloat162*>(ol)[2 * i + 1] = l23;
}

// ---------------------------------------------------------------------------
// Transpose + hi/lo split: out[c][r] = in[r][c], batched over z
// ---------------------------------------------------------------------------
__global__ __launch_bounds__(256)
void transpose_split(const float* __restrict__ in, long long inBS, int R, int C,
                     __nv_bfloat16* __restrict__ oh, __nv_bfloat16* __restrict__ ol,
                     int oLd, long long oBS)
{
    __shared__ float tile[32][33];
    const int z = blockIdx.z;
    const float* ip = in + (long long)z * inBS;
    const int c0 = blockIdx.x * 32;
    const int r0 = blockIdx.y * 32;
    const int tx = threadIdx.x;
    const int ty = threadIdx.y;

#pragma unroll
    for (int i = 0; i < 32; i += 8)
        tile[ty + i][tx] = ip[(long long)(r0 + ty + i) * C + c0 + tx];
    __syncthreads();

    const long long ob = (long long)z * oBS;
#pragma unroll
    for (int i = 0; i < 32; i += 8) {
        float v = tile[tx][ty + i];
        __nv_bfloat16 h = __float2bfloat16(v);
        float lo = v - __bfloat162float(h);
        long long o = ob + (long long)(c0 + ty + i) * oLd + r0 + tx;
        oh[o] = h;
        ol[o] = __float2bfloat16(lo);
    }
}

// ---------------------------------------------------------------------------
// Softmax over rows of 2048 -> bf16 hi/lo split probabilities
// ---------------------------------------------------------------------------
__global__ __launch_bounds__(256)
void softmax_split(const float* __restrict__ S,
                   __nv_bfloat16* __restrict__ PH, __nv_bfloat16* __restrict__ PL)
{
    const long long row = blockIdx.x;
    const float* p = S + row * (long long)BT;
    const int tid = threadIdx.x;

    float v[8];
    float m = -1e30f;
#pragma unroll
    for (int i = 0; i < 8; i++) {
        v[i] = p[tid + i * 256];
        m = fmaxf(m, v[i]);
    }
    __shared__ float red[256];
    red[tid] = m;
    __syncthreads();
    for (int s = 128; s > 0; s >>= 1) {
        if (tid < s) red[tid] = fmaxf(red[tid], red[tid + s]);
        __syncthreads();
    }
    m = red[0];
    __syncthreads();

    float sum = 0.0f;
#pragma unroll
    for (int i = 0; i < 8; i++) {
        v[i] = __expf(v[i] - m);
        sum += v[i];
    }
    red[tid] = sum;
    __syncthreads();
    for (int s = 128; s > 0; s >>= 1) {
        if (tid < s) red[tid] += red[tid + s];
        __syncthreads();
    }
    const float inv = 1.0f / red[0];
    __nv_bfloat16* ph = PH + row * (long long)BT;
    __nv_bfloat16* pl = PL + row * (long long)BT;
#pragma unroll
    for (int i = 0; i < 8; i++) {
        float pv = v[i] * inv;
        __nv_bfloat16 h = __float2bfloat16(pv);
        float lo = pv - __bfloat162float(h);
        ph[tid + i * 256] = h;
        pl[tid + i * 256] = __float2bfloat16(lo);
    }
}

// ---------------------------------------------------------------------------
// HMMA bf16-split GEMM, 3-stage cp.async pipeline, 128x128 tile, KC=64.
// C = alpha * (Ahi+Alo) @ (Bhi+Blo)^T   (3 terms: hh + hl + lh)
// A rows K-major (lda), B rows (pre-transposed) K-major (ldb).
// STAGE==1: plain; epilogue bf16 hi/lo split to Chi/Clo (ldc).
// STAGE==3: z=(b,h) batch; A,B are xq/xk slices; epilogue fp32*alpha -> scores.
// STAGE==4: A=P flat (b,h,t); B=xT per batch; epilogue ctx hi/lo scatter.
// STAGE==5: plain; epilogue fp32.
// ---------------------------------------------------------------------------
#define HTM 128
#define HTN 128
#define HTK 64

#define BUFSTRIDE 65536          // 4 tiles x 16KB
#define AHI_O 0
#define ALO_O 16384
#define BHI_O 32768
#define BLO_O 49152
#define HMMA_SMEM (3 * BUFSTRIDE)   // 192 KB

template <int STAGE>
__global__ __launch_bounds__(256, 1)
void hmma_gemm(const __nv_bfloat16* __restrict__ Ahi, const __nv_bfloat16* __restrict__ Alo,
               int lda,
               const __nv_bfloat16* __restrict__ Bhi, const __nv_bfloat16* __restrict__ Blo,
               int ldb,
               float* __restrict__ Cf,
               __nv_bfloat16* __restrict__ Chi, __nv_bfloat16* __restrict__ Clo,
               int ldc, int K, float alpha)
{
    extern __shared__ char smem[];
    const uint32_t sb = smem_u32(smem);
    const int tid  = threadIdx.x;
    const int wid  = tid >> 5;
    const int lane = tid & 31;
    const int mw = wid & 3;    // 4 M-warps (32 rows each)
    const int nw = wid >> 2;   // 2 N-warps (64 cols each)

    const long long m0 = (long long)blockIdx.y * HTM;
    const int n0 = blockIdx.x * HTN;

    const __nv_bfloat16 *Abh, *Abl, *Bbh, *Bbl;
    if (STAGE == 3) {
        const int z = blockIdx.z;
        const int b = z >> 4;
        const int h = z & 15;
        const long long ao = ((long long)b * BT + m0) * lda + h * BRANK;
        const long long bo = ((long long)b * BT + n0) * ldb + h * BRANK;
        Abh = Ahi + ao;  Abl = Alo + ao;
        Bbh = Bhi + bo;  Bbl = Blo + bo;
    } else if (STAGE == 4) {
        const long long b = m0 >> 15;    // 32768 flat rows per batch
        Abh = Ahi + m0 * lda;  Abl = Alo + m0 * lda;
        const long long bo = b * ((long long)BDIM * BT) + (long long)n0 * ldb;
        Bbh = Bhi + bo;  Bbl = Blo + bo;
    } else {
        Abh = Ahi + m0 * lda;  Abl = Alo + m0 * lda;
        Bbh = Bhi + (long long)n0 * ldb;  Bbl = Blo + (long long)n0 * ldb;
    }

    float acc[2][8][4];
#pragma unroll
    for (int i = 0; i < 2; i++)
#pragma unroll
        for (int f = 0; f < 8; f++)
#pragma unroll
            for (int e = 0; e < 4; e++) acc[i][f][e] = 0.0f;

    const int NC = K / HTK;

    auto load_chunk = [&](int c, int buf) {
        const long long kg = (long long)c * HTK;
        const uint32_t bb = sb + buf * BUFSTRIDE;
#pragma unroll
        for (int i = 0; i < 4; i++) {
            const int idx = tid + i * 256;
            const int r  = idx >> 3;
            const int ck = idx & 7;
            const uint32_t so = (uint32_t)(r * 128 + ((ck ^ (r & 7)) << 4));
            const long long ga = (long long)r * lda + kg + ck * 8;
            const long long gb = (long long)r * ldb + kg + ck * 8;
            CP16(bb + AHI_O + so, (const void*)(Abh + ga));
            CP16(bb + ALO_O + so, (const void*)(Abl + ga));
            CP16(bb + BHI_O + so, (const void*)(Bbh + gb));
            CP16(bb + BLO_O + so, (const void*)(Bbl + gb));
        }
        asm volatile("cp.async.commit_group;" ::: "memory");
    };

    load_chunk(0, 0);
    if (NC > 1) load_chunk(1, 1);

    for (int c = 0; c < NC; c++) {
        if (c + 2 < NC) load_chunk(c + 2, (c + 2) % 3);
        const int pend = (NC - 1 - c >= 2) ? 2 : (NC - 1 - c);
        if (pend == 2)      cp_wait<2>();
        else if (pend == 1) cp_wait<1>();
        else                cp_wait<0>();
        __syncthreads();

        const uint32_t ab = sb + (c % 3) * BUFSTRIDE;
#pragma unroll
        for (int ks = 0; ks < 4; ks++) {
            uint32_t ah[2][4], al[2][4], bh[4][4], bl[4][4];
#pragma unroll
            for (int i = 0; i < 2; i++) {
                const int r  = mw * 32 + i * 16 + (lane & 15);
                const int ck = ks * 2 + (lane >> 4);
                const uint32_t off = (uint32_t)(r * 128 + ((ck ^ (r & 7)) << 4));
                ldsm4(ah[i], ab + AHI_O + off);
                ldsm4(al[i], ab + ALO_O + off);
            }
#pragma unroll
            for (int j = 0; j < 4; j++) {
                const int r  = nw * 64 + j * 16 + (lane & 7) + ((lane >> 4) & 1) * 8;
                const int ck = ks * 2 + ((lane >> 3) & 1);
                const uint32_t off = (uint32_t)(r * 128 + ((ck ^ (r & 7)) << 4));
                ldsm4(bh[j], ab + BHI_O + off);
                ldsm4(bl[j], ab + BLO_O + off);
            }
#pragma unroll
            for (int i = 0; i < 2; i++)
#pragma unroll
                for (int f = 0; f < 8; f++) {
                    const uint32_t* Bh = &bh[f >> 1][(f & 1) * 2];
                    const uint32_t* Bl = &bl[f >> 1][(f & 1) * 2];
                    mma16816(acc[i][f], ah[i], Bh);
                    mma16816(acc[i][f], ah[i], Bl);
                    mma16816(acc[i][f], al[i], Bh);
                }
        }
        __syncthreads();
    }

    // Epilogue
#pragma unroll
    for (int i = 0; i < 2; i++) {
#pragma unroll
        for (int hr = 0; hr < 2; hr++) {
            const long long mg = m0 + mw * 32 + i * 16 + hr * 8 + (lane >> 2);
            const int ncol = n0 + nw * 64 + (lane & 3) * 2;
            if (STAGE == 5) {
                float* dst = Cf + mg * ldc + ncol;
#pragma unroll
                for (int f = 0; f < 8; f++) {
                    float2 v;
                    v.x = acc[i][f][hr * 2 + 0];
                    v.y = acc[i][f][hr * 2 + 1];
                    *reinterpret_cast<float2*>(dst + f * 8) = v;
                }
            } else if (STAGE == 3) {
                float* dst = Cf + (long long)blockIdx.z * BT * BT + mg * ldc + ncol;
#pragma unroll
                for (int f = 0; f < 8; f++) {
                    float2 v;
                    v.x = acc[i][f][hr * 2 + 0] * alpha;
                    v.y = acc[i][f][hr * 2 + 1] * alpha;
                    *reinterpret_cast<float2*>(dst + f * 8) = v;
                }
            } else if (STAGE == 1) {
                const long long orow = mg * ldc + ncol;
#pragma unroll
                for (int f = 0; f < 8; f++) {
                    const float v0 = acc[i][f][hr * 2 + 0];
                    const float v1 = acc[i][f][hr * 2 + 1];
                    __nv_bfloat162 hv, lv;
                    hv.x = __float2bfloat16(v0);
                    hv.y = __float2bfloat16(v1);
                    lv.x = __float2bfloat16(v0 - __bfloat162float(hv.x));
                    lv.y = __float2bfloat16(v1 - __bfloat162float(hv.y));
                    *reinterpret_cast<__nv_bfloat162*>(Chi + orow + f * 8) = hv;
                    *reinterpret_cast<__nv_bfloat162*>(Clo + orow + f * 8) = lv;
                }
            } else { // STAGE == 4
                const int b = (int)(mg >> 15);
                const int h = (int)((mg >> 11) & 15);
                const int t = (int)(mg & 2047);
                const long long orow =
                    ((long long)b * BT + t) * ((long long)BHEADS * BDIM) +
                    (long long)h * BDIM + ncol;
#pragma unroll
                for (int f = 0; f < 8; f++) {
                    const float v0 = acc[i][f][hr * 2 + 0];
                    const float v1 = acc[i][f][hr * 2 + 1];
                    __nv_bfloat162 hv, lv;
                    hv.x = __float2bfloat16(v0);
                    hv.y = __float2bfloat16(v1);
                    lv.x = __float2bfloat16(v0 - __bfloat162float(hv.x));
                    lv.y = __float2bfloat16(v1 - __bfloat162float(hv.y));
                    *reinterpret_cast<__nv_bfloat162*>(Chi + orow + f * 8) = hv;
                    *reinterpret_cast<__nv_bfloat162*>(Clo + orow + f * 8) = lv;
                }
            }
        }
    }
}

// ---------------------------------------------------------------------------
// Launch
// ---------------------------------------------------------------------------
extern "C" void kernel_launch(void* const* d_in, const int* in_sizes, int n_in,
                              void* d_out, int out_size)
{
    const float* x  = (const float*)d_in[0];   // [2,2048,1024]
    const float* Q  = (const float*)d_in[1];   // [16,64,1024]
    const float* K  = (const float*)d_in[2];
    const float* VO = (const float*)d_in[3];   // [16,1024,1024]
    float* out = (float*)d_out;                // [2,2048,1024]

    float *sc;
    __nv_bfloat16 *phi, *plo, *xhi, *xlo, *qhi, *qlo, *khi, *klo;
    __nv_bfloat16 *xqhi, *xqlo, *xkhi, *xklo;
    __nv_bfloat16 *xthi, *xtlo, *ctxhi, *ctxlo, *vothi, *votlo;
    cudaGetSymbolAddress((void**)&sc,    g_scores);
    cudaGetSymbolAddress((void**)&phi,   g_phi);
    cudaGetSymbolAddress((void**)&plo,   g_plo);
    cudaGetSymbolAddress((void**)&xhi,   g_xhi);
    cudaGetSymbolAddress((void**)&xlo,   g_xlo);
    cudaGetSymbolAddress((void**)&qhi,   g_qhi);
    cudaGetSymbolAddress((void**)&qlo,   g_qlo);
    cudaGetSymbolAddress((void**)&khi,   g_khi);
    cudaGetSymbolAddress((void**)&klo,   g_klo);
    cudaGetSymbolAddress((void**)&xqhi,  g_xqhi);
    cudaGetSymbolAddress((void**)&xqlo,  g_xqlo);
    cudaGetSymbolAddress((void**)&xkhi,  g_xkhi);
    cudaGetSymbolAddress((void**)&xklo,  g_xklo);
    cudaGetSymbolAddress((void**)&xthi,  g_xthi);
    cudaGetSymbolAddress((void**)&xtlo,  g_xtlo);
    cudaGetSymbolAddress((void**)&ctxhi, g_ctxhi);
    cudaGetSymbolAddress((void**)&ctxlo, g_ctxlo);
    cudaGetSymbolAddress((void**)&vothi, g_vothi);
    cudaGetSymbolAddress((void**)&votlo, g_votlo);

    cudaFuncSetAttribute(hmma_gemm<1>, cudaFuncAttributeMaxDynamicSharedMemorySize, HMMA_SMEM);
    cudaFuncSetAttribute(hmma_gemm<3>, cudaFuncAttributeMaxDynamicSharedMemorySize, HMMA_SMEM);
    cudaFuncSetAttribute(hmma_gemm<4>, cudaFuncAttributeMaxDynamicSharedMemorySize, HMMA_SMEM);
    cudaFuncSetAttribute(hmma_gemm<5>, cudaFuncAttributeMaxDynamicSharedMemorySize, HMMA_SMEM);

    const int MBT = BB * BT;                  // 4096
    const int HR  = BHEADS * BRANK;           // 1024
    const int HD  = BHEADS * BDIM;            // 16384

    // Input splits
    split_f32<<<(MBT * BDIM / 4 + 255) / 256, 256>>>(x, xhi, xlo, (long long)MBT * BDIM / 4);
    split_f32<<<(HR * BDIM / 4 + 255) / 256, 256>>>(Q, qhi, qlo, (long long)HR * BDIM / 4);
    split_f32<<<(HR * BDIM / 4 + 255) / 256, 256>>>(K, khi, klo, (long long)HR * BDIM / 4);
    transpose_split<<<dim3(BDIM / 32, BT / 32, BB), dim3(32, 8)>>>(
        x, (long long)BT * BDIM, BT, BDIM, xthi, xtlo, BT, (long long)BDIM * BT);
    transpose_split<<<dim3(BDIM / 32, BDIM / 32, BHEADS), dim3(32, 8)>>>(
        VO, (long long)BDIM * BDIM, BDIM, BDIM, vothi, votlo, HD, (long long)BDIM);

    // 1) xq = x @ Q^T  -> split   M=4096, N=1024, K=1024
    hmma_gemm<1><<<dim3(HR / HTN, MBT / HTM), 256, HMMA_SMEM>>>(
        xhi, xlo, BDIM, qhi, qlo, BDIM, nullptr, xqhi, xqlo, HR, BDIM, 1.0f);
    // 2) xk = x @ K^T  -> split
    hmma_gemm<1><<<dim3(HR / HTN, MBT / HTM), 256, HMMA_SMEM>>>(
        xhi, xlo, BDIM, khi, klo, BDIM, nullptr, xkhi, xklo, HR, BDIM, 1.0f);
    // 3) scores = xq @ xk^T / 32 per (b,h)   M=N=2048, K=64
    hmma_gemm<3><<<dim3(BT / HTN, BT / HTM, BB * BHEADS), 256, HMMA_SMEM>>>(
        xqhi, xqlo, HR, xkhi, xklo, HR, sc, nullptr, nullptr, BT, BRANK, 0.03125f);
    // 4) softmax -> P hi/lo
    softmax_split<<<BB * BHEADS * BT, 256>>>(sc, phi, plo);
    // 5) ctx = P @ x   M=65536 flat, N=1024, K=2048
    hmma_gemm<4><<<dim3(BDIM / HTN, (BB * BHEADS * BT) / HTM), 256, HMMA_SMEM>>>(
        phi, plo, BT, xthi, xtlo, BT, nullptr, ctxhi, ctxlo, 0, BT, 1.0f);
    // 6) out = ctx @ VO   M=4096, N=1024, K=16384
    hmma_gemm<5><<<dim3(BDIM / HTN, MBT / HTM), 256, HMMA_SMEM>>>(
        ctxhi, ctxlo, HD, vothi, votlo, HD, out, nullptr, nullptr, BDIM, HD, 1.0f);
}

// round 5
// speedup vs baseline: 3.0568x; 1.0244x over previous
#include <cuda_runtime.h>
#include <cuda_bf16.h>
#include <cstdint>

// Problem constants
#define BDIM   1024
#define BRANK  64
#define BHEADS 16
#define BB     2
#define BT     2048

// ---------------------------------------------------------------------------
// Scratch (device globals)
// ---------------------------------------------------------------------------
// E = exp(scores) hi/lo (bf16), written directly by stage-3 epilogue
__device__ __align__(256) __nv_bfloat16 g_phi[(size_t)BB * BHEADS * BT * BT];
__device__ __align__(256) __nv_bfloat16 g_plo[(size_t)BB * BHEADS * BT * BT];
__device__ __align__(256) float g_rinv[(size_t)BB * BHEADS * BT];   // 1/rowsum
// row-major splits of inputs
__device__ __align__(256) __nv_bfloat16 g_xhi[(size_t)BB * BT * BDIM];
__device__ __align__(256) __nv_bfloat16 g_xlo[(size_t)BB * BT * BDIM];
__device__ __align__(256) __nv_bfloat16 g_qhi[(size_t)BHEADS * BRANK * BDIM];
__device__ __align__(256) __nv_bfloat16 g_qlo[(size_t)BHEADS * BRANK * BDIM];
__device__ __align__(256) __nv_bfloat16 g_khi[(size_t)BHEADS * BRANK * BDIM];
__device__ __align__(256) __nv_bfloat16 g_klo[(size_t)BHEADS * BRANK * BDIM];
// projections (split, written by HMMA epilogue)
__device__ __align__(256) __nv_bfloat16 g_xqhi[(size_t)BB * BT * BHEADS * BRANK];
__device__ __align__(256) __nv_bfloat16 g_xqlo[(size_t)BB * BT * BHEADS * BRANK];
__device__ __align__(256) __nv_bfloat16 g_xkhi[(size_t)BB * BT * BHEADS * BRANK];
__device__ __align__(256) __nv_bfloat16 g_xklo[(size_t)BB * BT * BHEADS * BRANK];
// x transposed per batch: [b][d][u]
__device__ __align__(256) __nv_bfloat16 g_xthi[(size_t)BB * BDIM * BT];
__device__ __align__(256) __nv_bfloat16 g_xtlo[(size_t)BB * BDIM * BT];
// ctx split: [bt][h*D+d]
__device__ __align__(256) __nv_bfloat16 g_ctxhi[(size_t)BB * BT * BHEADS * BDIM];
__device__ __align__(256) __nv_bfloat16 g_ctxlo[(size_t)BB * BT * BHEADS * BDIM];
// VO transposed: [e][h*D+d]
__device__ __align__(256) __nv_bfloat16 g_vothi[(size_t)BDIM * BHEADS * BDIM];
__device__ __align__(256) __nv_bfloat16 g_votlo[(size_t)BDIM * BHEADS * BDIM];

// ---------------------------------------------------------------------------
// Helpers
// ---------------------------------------------------------------------------
__device__ __forceinline__ uint32_t smem_u32(const void* p) {
    return (uint32_t)__cvta_generic_to_shared(p);
}

#define CP16(s, g) asm volatile("cp.async.cg.shared.global [%0], [%1], 16;" :: "r"(s), "l"(g))

__device__ __forceinline__ void ldsm4(uint32_t* r, uint32_t addr) {
    asm volatile("ldmatrix.sync.aligned.m8n8.x4.shared.b16 {%0,%1,%2,%3}, [%4];"
        : "=r"(r[0]), "=r"(r[1]), "=r"(r[2]), "=r"(r[3]) : "r"(addr));
}

__device__ __forceinline__ void mma16816(float* c, const uint32_t* a, const uint32_t* b) {
    asm volatile("mma.sync.aligned.m16n8k16.row.col.f32.bf16.bf16.f32 "
        "{%0,%1,%2,%3}, {%4,%5,%6,%7}, {%8,%9}, {%0,%1,%2,%3};"
        : "+f"(c[0]), "+f"(c[1]), "+f"(c[2]), "+f"(c[3])
        : "r"(a[0]), "r"(a[1]), "r"(a[2]), "r"(a[3]), "r"(b[0]), "r"(b[1]));
}

template <int N>
__device__ __forceinline__ void cp_wait() {
    asm volatile("cp.async.wait_group %0;" :: "n"(N) : "memory");
}

// ---------------------------------------------------------------------------
// Elementwise hi/lo split: fp32 -> bf16 hi + bf16 lo (float4 per thread)
// ---------------------------------------------------------------------------
__global__ __launch_bounds__(256)
void split_f32(const float* __restrict__ in,
               __nv_bfloat16* __restrict__ oh, __nv_bfloat16* __restrict__ ol,
               long long n4)
{
    const long long i = (long long)blockIdx.x * 256 + threadIdx.x;
    if (i >= n4) return;
    float4 v = reinterpret_cast<const float4*>(in)[i];
    __nv_bfloat162 h01, h23, l01, l23;
    h01.x = __float2bfloat16(v.x); h01.y = __float2bfloat16(v.y);
    h23.x = __float2bfloat16(v.z); h23.y = __float2bfloat16(v.w);
    l01.x = __float2bfloat16(v.x - __bfloat162float(h01.x));
    l01.y = __float2bfloat16(v.y - __bfloat162float(h01.y));
    l23.x = __float2bfloat16(v.z - __bfloat162float(h23.x));
    l23.y = __float2bfloat16(v.w - __bfloat162float(h23.y));
    reinterpret_cast<__nv_bfloat162*>(oh)[2 * i + 0] = h01;
    reinterpret_cast<__nv_bfloat162*>(oh)[2 * i + 1] = h23;
    reinterpret_cast<__nv_bfloat162*>(ol)[2 * i + 0] = l01;
    reinterpret_cast<__nv_bfloat162*>(ol)[2 * i + 1] = l23;
}

// ---------------------------------------------------------------------------
// Transpose + hi/lo split: out[c][r] = in[r][c], batched over z
// ---------------------------------------------------------------------------
__global__ __launch_bounds__(256)
void transpose_split(const float* __restrict__ in, long long inBS, int R, int C,
                     __nv_bfloat16* __restrict__ oh, __nv_bfloat16* __restrict__ ol,
                     int oLd, long long oBS)
{
    __shared__ float tile[32][33];
    const int z = blockIdx.z;
    const float* ip = in + (long long)z * inBS;
    const int c0 = blockIdx.x * 32;
    const int r0 = blockIdx.y * 32;
    const int tx = threadIdx.x;
    const int ty = threadIdx.y;

#pragma unroll
    for (int i = 0; i < 32; i += 8)
        tile[ty + i][tx] = ip[(long long)(r0 + ty + i) * C + c0 + tx];
    __syncthreads();

    const long long ob = (long long)z * oBS;
#pragma unroll
    for (int i = 0; i < 32; i += 8) {
        float v = tile[tx][ty + i];
        __nv_bfloat16 h = __float2bfloat16(v);
        float lo = v - __bfloat162float(h);
        long long o = ob + (long long)(c0 + ty + i) * oLd + r0 + tx;
        oh[o] = h;
        ol[o] = __float2bfloat16(lo);
    }
}

// ---------------------------------------------------------------------------
// Row sums of E (hi+lo) over rows of 2048 -> inverse
// ---------------------------------------------------------------------------
__global__ __launch_bounds__(256)
void rowsum_inv(const __nv_bfloat16* __restrict__ EH,
                const __nv_bfloat16* __restrict__ EL,
                float* __restrict__ inv)
{
    const long long row = blockIdx.x;
    const int tid = threadIdx.x;
    const uint4* ph = reinterpret_cast<const uint4*>(EH + row * (long long)BT);
    const uint4* pl = reinterpret_cast<const uint4*>(EL + row * (long long)BT);
    uint4 h = ph[tid];
    uint4 l = pl[tid];
    float s = 0.0f;
    {
        const uint32_t hw[4] = {h.x, h.y, h.z, h.w};
        const uint32_t lw[4] = {l.x, l.y, l.z, l.w};
#pragma unroll
        for (int i = 0; i < 4; i++) {
            __nv_bfloat162 hv = *reinterpret_cast<const __nv_bfloat162*>(&hw[i]);
            __nv_bfloat162 lv = *reinterpret_cast<const __nv_bfloat162*>(&lw[i]);
            s += __bfloat162float(hv.x) + __bfloat162float(hv.y);
            s += __bfloat162float(lv.x) + __bfloat162float(lv.y);
        }
    }
    __shared__ float red[256];
    red[tid] = s;
    __syncthreads();
    for (int st = 128; st > 0; st >>= 1) {
        if (tid < st) red[tid] += red[tid + st];
        __syncthreads();
    }
    if (tid == 0) inv[row] = 1.0f / red[0];
}

// ---------------------------------------------------------------------------
// HMMA bf16-split GEMM, 3-stage cp.async pipeline, 128x128 tile, KC=64.
// C = (Ahi+Alo) @ (Bhi+Blo)^T   (3 terms: hh + hl + lh)
// STAGE==1: epilogue bf16 hi/lo split -> Chi/Clo.
// STAGE==3: z=(b,h); A,B = xq/xk slices; epilogue exp(acc*alpha) hi/lo -> E.
// STAGE==4: A=E flat (b,h,t); B=xT per batch; epilogue *= Rinv[row], hi/lo ctx scatter.
// STAGE==5: epilogue fp32.
// ---------------------------------------------------------------------------
#define HTM 128
#define HTN 128
#define HTK 64

#define BUFSTRIDE 65536          // 4 tiles x 16KB
#define AHI_O 0
#define ALO_O 16384
#define BHI_O 32768
#define BLO_O 49152
#define HMMA_SMEM (3 * BUFSTRIDE)   // 192 KB

template <int STAGE>
__global__ __launch_bounds__(256, (STAGE == 3) ? 2 : 1)
void hmma_gemm(const __nv_bfloat16* __restrict__ Ahi, const __nv_bfloat16* __restrict__ Alo,
               int lda,
               const __nv_bfloat16* __restrict__ Bhi, const __nv_bfloat16* __restrict__ Blo,
               int ldb,
               float* __restrict__ Cf,
               __nv_bfloat16* __restrict__ Chi, __nv_bfloat16* __restrict__ Clo,
               const float* __restrict__ Rinv,
               int ldc, int K, float alpha)
{
    extern __shared__ char smem[];
    const uint32_t sb = smem_u32(smem);
    const int tid  = threadIdx.x;
    const int wid  = tid >> 5;
    const int lane = tid & 31;
    const int mw = wid & 3;    // 4 M-warps (32 rows each)
    const int nw = wid >> 2;   // 2 N-warps (64 cols each)

    const long long m0 = (long long)blockIdx.y * HTM;
    const int n0 = blockIdx.x * HTN;

    const __nv_bfloat16 *Abh, *Abl, *Bbh, *Bbl;
    if (STAGE == 3) {
        const int z = blockIdx.z;
        const int b = z >> 4;
        const int h = z & 15;
        const long long ao = ((long long)b * BT + m0) * lda + h * BRANK;
        const long long bo = ((long long)b * BT + n0) * ldb + h * BRANK;
        Abh = Ahi + ao;  Abl = Alo + ao;
        Bbh = Bhi + bo;  Bbl = Blo + bo;
    } else if (STAGE == 4) {
        const long long b = m0 >> 15;    // 32768 flat rows per batch
        Abh = Ahi + m0 * lda;  Abl = Alo + m0 * lda;
        const long long bo = b * ((long long)BDIM * BT) + (long long)n0 * ldb;
        Bbh = Bhi + bo;  Bbl = Blo + bo;
    } else {
        Abh = Ahi + m0 * lda;  Abl = Alo + m0 * lda;
        Bbh = Bhi + (long long)n0 * ldb;  Bbl = Blo + (long long)n0 * ldb;
    }

    float acc[2][8][4];
#pragma unroll
    for (int i = 0; i < 2; i++)
#pragma unroll
        for (int f = 0; f < 8; f++)
#pragma unroll
            for (int e = 0; e < 4; e++) acc[i][f][e] = 0.0f;

    const int NC = K / HTK;

    auto load_chunk = [&](int c, int buf) {
        const long long kg = (long long)c * HTK;
        const uint32_t bb = sb + buf * BUFSTRIDE;
#pragma unroll
        for (int i = 0; i < 4; i++) {
            const int idx = tid + i * 256;
            const int r  = idx >> 3;
            const int ck = idx & 7;
            const uint32_t so = (uint32_t)(r * 128 + ((ck ^ (r & 7)) << 4));
            const long long ga = (long long)r * lda + kg + ck * 8;
            const long long gb = (long long)r * ldb + kg + ck * 8;
            CP16(bb + AHI_O + so, (const void*)(Abh + ga));
            CP16(bb + ALO_O + so, (const void*)(Abl + ga));
            CP16(bb + BHI_O + so, (const void*)(Bbh + gb));
            CP16(bb + BLO_O + so, (const void*)(Bbl + gb));
        }
        asm volatile("cp.async.commit_group;" ::: "memory");
    };

    load_chunk(0, 0);
    if (NC > 1) load_chunk(1, 1);

    for (int c = 0; c < NC; c++) {
        if (c + 2 < NC) load_chunk(c + 2, (c + 2) % 3);
        const int pend = (NC - 1 - c >= 2) ? 2 : (NC - 1 - c);
        if (pend == 2)      cp_wait<2>();
        else if (pend == 1) cp_wait<1>();
        else                cp_wait<0>();
        __syncthreads();

        const uint32_t ab = sb + (c % 3) * BUFSTRIDE;
#pragma unroll
        for (int ks = 0; ks < 4; ks++) {
            uint32_t ah[2][4], al[2][4], bh[4][4], bl[4][4];
#pragma unroll
            for (int i = 0; i < 2; i++) {
                const int r  = mw * 32 + i * 16 + (lane & 15);
                const int ck = ks * 2 + (lane >> 4);
                const uint32_t off = (uint32_t)(r * 128 + ((ck ^ (r & 7)) << 4));
                ldsm4(ah[i], ab + AHI_O + off);
                ldsm4(al[i], ab + ALO_O + off);
            }
#pragma unroll
            for (int j = 0; j < 4; j++) {
                const int r  = nw * 64 + j * 16 + (lane & 7) + ((lane >> 4) & 1) * 8;
                const int ck = ks * 2 + ((lane >> 3) & 1);
                const uint32_t off = (uint32_t)(r * 128 + ((ck ^ (r & 7)) << 4));
                ldsm4(bh[j], ab + BHI_O + off);
                ldsm4(bl[j], ab + BLO_O + off);
            }
#pragma unroll
            for (int i = 0; i < 2; i++)
#pragma unroll
                for (int f = 0; f < 8; f++) {
                    const uint32_t* Bh = &bh[f >> 1][(f & 1) * 2];
                    const uint32_t* Bl = &bl[f >> 1][(f & 1) * 2];
                    mma16816(acc[i][f], ah[i], Bh);
                    mma16816(acc[i][f], ah[i], Bl);
                    mma16816(acc[i][f], al[i], Bh);
                }
        }
        __syncthreads();
    }

    // Epilogue
#pragma unroll
    for (int i = 0; i < 2; i++) {
#pragma unroll
        for (int hr = 0; hr < 2; hr++) {
            const long long mg = m0 + mw * 32 + i * 16 + hr * 8 + (lane >> 2);
            const int ncol = n0 + nw * 64 + (lane & 3) * 2;
            if (STAGE == 5) {
                float* dst = Cf + mg * ldc + ncol;
#pragma unroll
                for (int f = 0; f < 8; f++) {
                    float2 v;
                    v.x = acc[i][f][hr * 2 + 0];
                    v.y = acc[i][f][hr * 2 + 1];
                    *reinterpret_cast<float2*>(dst + f * 8) = v;
                }
            } else if (STAGE == 3) {
                // E = exp(score) hi/lo, no max subtraction (scores bounded)
                const long long orow = (long long)blockIdx.z * BT * BT + mg * ldc + ncol;
#pragma unroll
                for (int f = 0; f < 8; f++) {
                    const float e0 = __expf(acc[i][f][hr * 2 + 0] * alpha);
                    const float e1 = __expf(acc[i][f][hr * 2 + 1] * alpha);
                    __nv_bfloat162 hv, lv;
                    hv.x = __float2bfloat16(e0);
                    hv.y = __float2bfloat16(e1);
                    lv.x = __float2bfloat16(e0 - __bfloat162float(hv.x));
                    lv.y = __float2bfloat16(e1 - __bfloat162float(hv.y));
                    *reinterpret_cast<__nv_bfloat162*>(Chi + orow + f * 8) = hv;
                    *reinterpret_cast<__nv_bfloat162*>(Clo + orow + f * 8) = lv;
                }
            } else if (STAGE == 1) {
                const long long orow = mg * ldc + ncol;
#pragma unroll
                for (int f = 0; f < 8; f++) {
                    const float v0 = acc[i][f][hr * 2 + 0];
                    const float v1 = acc[i][f][hr * 2 + 1];
                    __nv_bfloat162 hv, lv;
                    hv.x = __float2bfloat16(v0);
                    hv.y = __float2bfloat16(v1);
                    lv.x = __float2bfloat16(v0 - __bfloat162float(hv.x));
                    lv.y = __float2bfloat16(v1 - __bfloat162float(hv.y));
                    *reinterpret_cast<__nv_bfloat162*>(Chi + orow + f * 8) = hv;
                    *reinterpret_cast<__nv_bfloat162*>(Clo + orow + f * 8) = lv;
                }
            } else { // STAGE == 4
                const float rs = Rinv[mg];
                const int b = (int)(mg >> 15);
                const int h = (int)((mg >> 11) & 15);
                const int t = (int)(mg & 2047);
                const long long orow =
                    ((long long)b * BT + t) * ((long long)BHEADS * BDIM) +
                    (long long)h * BDIM + ncol;
#pragma unroll
                for (int f = 0; f < 8; f++) {
                    const float v0 = acc[i][f][hr * 2 + 0] * rs;
                    const float v1 = acc[i][f][hr * 2 + 1] * rs;
                    __nv_bfloat162 hv, lv;
                    hv.x = __float2bfloat16(v0);
                    hv.y = __float2bfloat16(v1);
                    lv.x = __float2bfloat16(v0 - __bfloat162float(hv.x));
                    lv.y = __float2bfloat16(v1 - __bfloat162float(hv.y));
                    *reinterpret_cast<__nv_bfloat162*>(Chi + orow + f * 8) = hv;
                    *reinterpret_cast<__nv_bfloat162*>(Clo + orow + f * 8) = lv;
                }
            }
        }
    }
}

// ---------------------------------------------------------------------------
// Launch
// ---------------------------------------------------------------------------
extern "C" void kernel_launch(void* const* d_in, const int* in_sizes, int n_in,
                              void* d_out, int out_size)
{
    const float* x  = (const float*)d_in[0];   // [2,2048,1024]
    const float* Q  = (const float*)d_in[1];   // [16,64,1024]
    const float* K  = (const float*)d_in[2];
    const float* VO = (const float*)d_in[3];   // [16,1024,1024]
    float* out = (float*)d_out;                // [2,2048,1024]

    float *rinv;
    __nv_bfloat16 *phi, *plo, *xhi, *xlo, *qhi, *qlo, *khi, *klo;
    __nv_bfloat16 *xqhi, *xqlo, *xkhi, *xklo;
    __nv_bfloat16 *xthi, *xtlo, *ctxhi, *ctxlo, *vothi, *votlo;
    cudaGetSymbolAddress((void**)&rinv,  g_rinv);
    cudaGetSymbolAddress((void**)&phi,   g_phi);
    cudaGetSymbolAddress((void**)&plo,   g_plo);
    cudaGetSymbolAddress((void**)&xhi,   g_xhi);
    cudaGetSymbolAddress((void**)&xlo,   g_xlo);
    cudaGetSymbolAddress((void**)&qhi,   g_qhi);
    cudaGetSymbolAddress((void**)&qlo,   g_qlo);
    cudaGetSymbolAddress((void**)&khi,   g_khi);
    cudaGetSymbolAddress((void**)&klo,   g_klo);
    cudaGetSymbolAddress((void**)&xqhi,  g_xqhi);
    cudaGetSymbolAddress((void**)&xqlo,  g_xqlo);
    cudaGetSymbolAddress((void**)&xkhi,  g_xkhi);
    cudaGetSymbolAddress((void**)&xklo,  g_xklo);
    cudaGetSymbolAddress((void**)&xthi,  g_xthi);
    cudaGetSymbolAddress((void**)&xtlo,  g_xtlo);
    cudaGetSymbolAddress((void**)&ctxhi, g_ctxhi);
    cudaGetSymbolAddress((void**)&ctxlo, g_ctxlo);
    cudaGetSymbolAddress((void**)&vothi, g_vothi);
    cudaGetSymbolAddress((void**)&votlo, g_votlo);

    cudaFuncSetAttribute(hmma_gemm<1>, cudaFuncAttributeMaxDynamicSharedMemorySize, HMMA_SMEM);
    cudaFuncSetAttribute(hmma_gemm<3>, cudaFuncAttributeMaxDynamicSharedMemorySize, HMMA_SMEM);
    cudaFuncSetAttribute(hmma_gemm<4>, cudaFuncAttributeMaxDynamicSharedMemorySize, HMMA_SMEM);
    cudaFuncSetAttribute(hmma_gemm<5>, cudaFuncAttributeMaxDynamicSharedMemorySize, HMMA_SMEM);

    const int MBT = BB * BT;                  // 4096
    const int HR  = BHEADS * BRANK;           // 1024
    const int HD  = BHEADS * BDIM;            // 16384

    // Input splits
    split_f32<<<(MBT * BDIM / 4 + 255) / 256, 256>>>(x, xhi, xlo, (long long)MBT * BDIM / 4);
    split_f32<<<(HR * BDIM / 4 + 255) / 256, 256>>>(Q, qhi, qlo, (long long)HR * BDIM / 4);
    split_f32<<<(HR * BDIM / 4 + 255) / 256, 256>>>(K, khi, klo, (long long)HR * BDIM / 4);
    transpose_split<<<dim3(BDIM / 32, BT / 32, BB), dim3(32, 8)>>>(
        x, (long long)BT * BDIM, BT, BDIM, xthi, xtlo, BT, (long long)BDIM * BT);
    transpose_split<<<dim3(BDIM / 32, BDIM / 32, BHEADS), dim3(32, 8)>>>(
        VO, (long long)BDIM * BDIM, BDIM, BDIM, vothi, votlo, HD, (long long)BDIM);

    // 1) xq = x @ Q^T  -> split   M=4096, N=1024, K=1024
    hmma_gemm<1><<<dim3(HR / HTN, MBT / HTM), 256, HMMA_SMEM>>>(
        xhi, xlo, BDIM, qhi, qlo, BDIM, nullptr, xqhi, xqlo, nullptr, HR, BDIM, 1.0f);
    // 2) xk = x @ K^T  -> split
    hmma_gemm<1><<<dim3(HR / HTN, MBT / HTM), 256, HMMA_SMEM>>>(
        xhi, xlo, BDIM, khi, klo, BDIM, nullptr, xkhi, xklo, nullptr, HR, BDIM, 1.0f);
    // 3) E = exp(xq @ xk^T / 32) per (b,h) -> hi/lo   M=N=2048, K=64 (single buffer)
    hmma_gemm<3><<<dim3(BT / HTN, BT / HTM, BB * BHEADS), 256, BUFSTRIDE>>>(
        xqhi, xqlo, HR, xkhi, xklo, HR, nullptr, phi, plo, nullptr, BT, BRANK, 0.03125f);
    // 4) inverse row sums of E
    rowsum_inv<<<BB * BHEADS * BT, 256>>>(phi, plo, rinv);
    // 5) ctx = (E @ x) * rinv   M=65536 flat, N=1024, K=2048
    hmma_gemm<4><<<dim3(BDIM / HTN, (BB * BHEADS * BT) / HTM), 256, HMMA_SMEM>>>(
        phi, plo, BT, xthi, xtlo, BT, nullptr, ctxhi, ctxlo, rinv, 0, BT, 1.0f);
    // 6) out = ctx @ VO   M=4096, N=1024, K=16384
    hmma_gemm<5><<<dim3(BDIM / HTN, MBT / HTM), 256, HMMA_SMEM>>>(
        ctxhi, ctxlo, HD, vothi, votlo, HD, out, nullptr, nullptr, nullptr, BDIM, HD, 1.0f);
}

// round 6
// speedup vs baseline: 3.1314x; 1.0244x over previous
#include <cuda_runtime.h>
#include <cuda_bf16.h>
#include <cstdint>

// Problem constants
#define BDIM   1024
#define BRANK  64
#define BHEADS 16
#define BB     2
#define BT     2048

// ---------------------------------------------------------------------------
// Scratch (device globals)
// ---------------------------------------------------------------------------
// E = exp(scores) hi/lo (bf16), written directly by stage-3 epilogue
__device__ __align__(256) __nv_bfloat16 g_phi[(size_t)BB * BHEADS * BT * BT];
__device__ __align__(256) __nv_bfloat16 g_plo[(size_t)BB * BHEADS * BT * BT];
__device__ __align__(256) float g_part[(size_t)BB * BHEADS * BT * 16];  // per-colblock partial sums
__device__ __align__(256) float g_rinv[(size_t)BB * BHEADS * BT];       // 1/rowsum
// row-major splits of inputs
__device__ __align__(256) __nv_bfloat16 g_xhi[(size_t)BB * BT * BDIM];
__device__ __align__(256) __nv_bfloat16 g_xlo[(size_t)BB * BT * BDIM];
// Q and K stacked: rows [0,1024) = Q, [1024,2048) = K
__device__ __align__(256) __nv_bfloat16 g_qkhi[(size_t)2 * BHEADS * BRANK * BDIM];
__device__ __align__(256) __nv_bfloat16 g_qklo[(size_t)2 * BHEADS * BRANK * BDIM];
// projections (split, written by HMMA epilogue)
__device__ __align__(256) __nv_bfloat16 g_xqhi[(size_t)BB * BT * BHEADS * BRANK];
__device__ __align__(256) __nv_bfloat16 g_xqlo[(size_t)BB * BT * BHEADS * BRANK];
__device__ __align__(256) __nv_bfloat16 g_xkhi[(size_t)BB * BT * BHEADS * BRANK];
__device__ __align__(256) __nv_bfloat16 g_xklo[(size_t)BB * BT * BHEADS * BRANK];
// x transposed per batch: [b][d][u]
__device__ __align__(256) __nv_bfloat16 g_xthi[(size_t)BB * BDIM * BT];
__device__ __align__(256) __nv_bfloat16 g_xtlo[(size_t)BB * BDIM * BT];
// ctx split: [bt][h*D+d]
__device__ __align__(256) __nv_bfloat16 g_ctxhi[(size_t)BB * BT * BHEADS * BDIM];
__device__ __align__(256) __nv_bfloat16 g_ctxlo[(size_t)BB * BT * BHEADS * BDIM];
// VO transposed: [e][h*D+d]
__device__ __align__(256) __nv_bfloat16 g_vothi[(size_t)BDIM * BHEADS * BDIM];
__device__ __align__(256) __nv_bfloat16 g_votlo[(size_t)BDIM * BHEADS * BDIM];

// ---------------------------------------------------------------------------
// Helpers
// ---------------------------------------------------------------------------
__device__ __forceinline__ uint32_t smem_u32(const void* p) {
    return (uint32_t)__cvta_generic_to_shared(p);
}

#define CP16(s, g) asm volatile("cp.async.cg.shared.global [%0], [%1], 16;" :: "r"(s), "l"(g))

__device__ __forceinline__ void ldsm4(uint32_t* r, uint32_t addr) {
    asm volatile("ldmatrix.sync.aligned.m8n8.x4.shared.b16 {%0,%1,%2,%3}, [%4];"
        : "=r"(r[0]), "=r"(r[1]), "=r"(r[2]), "=r"(r[3]) : "r"(addr));
}

__device__ __forceinline__ void mma16816(float* c, const uint32_t* a, const uint32_t* b) {
    asm volatile("mma.sync.aligned.m16n8k16.row.col.f32.bf16.bf16.f32 "
        "{%0,%1,%2,%3}, {%4,%5,%6,%7}, {%8,%9}, {%0,%1,%2,%3};"
        : "+f"(c[0]), "+f"(c[1]), "+f"(c[2]), "+f"(c[3])
        : "r"(a[0]), "r"(a[1]), "r"(a[2]), "r"(a[3]), "r"(b[0]), "r"(b[1]));
}

template <int N>
__device__ __forceinline__ void cp_wait() {
    asm volatile("cp.async.wait_group %0;" :: "n"(N) : "memory");
}

// ---------------------------------------------------------------------------
// Elementwise hi/lo split: fp32 -> bf16 hi + bf16 lo (float4 per thread)
// ---------------------------------------------------------------------------
__global__ __launch_bounds__(256)
void split_f32(const float* __restrict__ in,
               __nv_bfloat16* __restrict__ oh, __nv_bfloat16* __restrict__ ol,
               long long n4)
{
    const long long i = (long long)blockIdx.x * 256 + threadIdx.x;
    if (i >= n4) return;
    float4 v = reinterpret_cast<const float4*>(in)[i];
    __nv_bfloat162 h01, h23, l01, l23;
    h01.x = __float2bfloat16(v.x); h01.y = __float2bfloat16(v.y);
    h23.x = __float2bfloat16(v.z); h23.y = __float2bfloat16(v.w);
    l01.x = __float2bfloat16(v.x - __bfloat162float(h01.x));
    l01.y = __float2bfloat16(v.y - __bfloat162float(h01.y));
    l23.x = __float2bfloat16(v.z - __bfloat162float(h23.x));
    l23.y = __float2bfloat16(v.w - __bfloat162float(h23.y));
    reinterpret_cast<__nv_bfloat162*>(oh)[2 * i + 0] = h01;
    reinterpret_cast<__nv_bfloat162*>(oh)[2 * i + 1] = h23;
    reinterpret_cast<__nv_bfloat162*>(ol)[2 * i + 0] = l01;
    reinterpret_cast<__nv_bfloat162*>(ol)[2 * i + 1] = l23;
}

// ---------------------------------------------------------------------------
// Transpose + hi/lo split: out[c][r] = in[r][c], batched over z
// ---------------------------------------------------------------------------
__global__ __launch_bounds__(256)
void transpose_split(const float* __restrict__ in, long long inBS, int R, int C,
                     __nv_bfloat16* __restrict__ oh, __nv_bfloat16* __restrict__ ol,
                     int oLd, long long oBS)
{
    __shared__ float tile[32][33];
    const int z = blockIdx.z;
    const float* ip = in + (long long)z * inBS;
    const int c0 = blockIdx.x * 32;
    const int r0 = blockIdx.y * 32;
    const int tx = threadIdx.x;
    const int ty = threadIdx.y;

#pragma unroll
    for (int i = 0; i < 32; i += 8)
        tile[ty + i][tx] = ip[(long long)(r0 + ty + i) * C + c0 + tx];
    __syncthreads();

    const long long ob = (long long)z * oBS;
#pragma unroll
    for (int i = 0; i < 32; i += 8) {
        float v = tile[tx][ty + i];
        __nv_bfloat16 h = __float2bfloat16(v);
        float lo = v - __bfloat162float(h);
        long long o = ob + (long long)(c0 + ty + i) * oLd + r0 + tx;
        oh[o] = h;
        ol[o] = __float2bfloat16(lo);
    }
}

// ---------------------------------------------------------------------------
// Reduce 16 per-row partials -> 1/rowsum
// ---------------------------------------------------------------------------
__global__ __launch_bounds__(256)
void reduce_inv(const float* __restrict__ part, float* __restrict__ inv)
{
    const long long r = (long long)blockIdx.x * 256 + threadIdx.x;
    const float4* p = reinterpret_cast<const float4*>(part + r * 16);
    float4 a = p[0], b = p[1], c = p[2], d = p[3];
    float s = ((a.x + a.y) + (a.z + a.w)) + ((b.x + b.y) + (b.z + b.w))
            + ((c.x + c.y) + (c.z + c.w)) + ((d.x + d.y) + (d.z + d.w));
    inv[r] = 1.0f / s;
}

// ---------------------------------------------------------------------------
// HMMA bf16-split GEMM, 3-stage cp.async pipeline, 128x128 tile, KC=64.
// C = (Ahi+Alo) @ (Bhi+Blo)^T   (3 terms: hh + hl + lh)
// STAGE==1: epilogue bf16 hi/lo split; dest = (Chi,Clo) for ncol<1024 (xq)
//           else (Chi2,Clo2) at ncol-1024 (xk).
// STAGE==3: z=(b,h); epilogue exp(acc*alpha) hi/lo -> E, plus per-row
//           deterministic partial sums -> Cf[row*16 + blockIdx.x].
// STAGE==4: A=E flat; B=xT per batch; epilogue *= Rinv[row], ctx hi/lo scatter.
// STAGE==5: epilogue fp32.
// ---------------------------------------------------------------------------
#define HTM 128
#define HTN 128
#define HTK 64

#define BUFSTRIDE 65536          // 4 tiles x 16KB
#define AHI_O 0
#define ALO_O 16384
#define BHI_O 32768
#define BLO_O 49152
#define HMMA_SMEM (3 * BUFSTRIDE)   // 192 KB

template <int STAGE>
__global__ __launch_bounds__(256, (STAGE == 3) ? 2 : 1)
void hmma_gemm(const __nv_bfloat16* __restrict__ Ahi, const __nv_bfloat16* __restrict__ Alo,
               int lda,
               const __nv_bfloat16* __restrict__ Bhi, const __nv_bfloat16* __restrict__ Blo,
               int ldb,
               float* __restrict__ Cf,
               __nv_bfloat16* __restrict__ Chi, __nv_bfloat16* __restrict__ Clo,
               __nv_bfloat16* __restrict__ Chi2, __nv_bfloat16* __restrict__ Clo2,
               const float* __restrict__ Rinv,
               int ldc, int K, float alpha)
{
    extern __shared__ char smem[];
    __shared__ float srow[2][HTM];
    const uint32_t sb = smem_u32(smem);
    const int tid  = threadIdx.x;
    const int wid  = tid >> 5;
    const int lane = tid & 31;
    const int mw = wid & 3;    // 4 M-warps (32 rows each)
    const int nw = wid >> 2;   // 2 N-warps (64 cols each)

    const long long m0 = (long long)blockIdx.y * HTM;
    const int n0 = blockIdx.x * HTN;

    const __nv_bfloat16 *Abh, *Abl, *Bbh, *Bbl;
    if (STAGE == 3) {
        const int z = blockIdx.z;
        const int b = z >> 4;
        const int h = z & 15;
        const long long ao = ((long long)b * BT + m0) * lda + h * BRANK;
        const long long bo = ((long long)b * BT + n0) * ldb + h * BRANK;
        Abh = Ahi + ao;  Abl = Alo + ao;
        Bbh = Bhi + bo;  Bbl = Blo + bo;
    } else if (STAGE == 4) {
        const long long b = m0 >> 15;    // 32768 flat rows per batch
        Abh = Ahi + m0 * lda;  Abl = Alo + m0 * lda;
        const long long bo = b * ((long long)BDIM * BT) + (long long)n0 * ldb;
        Bbh = Bhi + bo;  Bbl = Blo + bo;
    } else {
        Abh = Ahi + m0 * lda;  Abl = Alo + m0 * lda;
        Bbh = Bhi + (long long)n0 * ldb;  Bbl = Blo + (long long)n0 * ldb;
    }

    float acc[2][8][4];
#pragma unroll
    for (int i = 0; i < 2; i++)
#pragma unroll
        for (int f = 0; f < 8; f++)
#pragma unroll
            for (int e = 0; e < 4; e++) acc[i][f][e] = 0.0f;

    const int NC = K / HTK;

    auto load_chunk = [&](int c, int buf) {
        const long long kg = (long long)c * HTK;
        const uint32_t bb = sb + buf * BUFSTRIDE;
#pragma unroll
        for (int i = 0; i < 4; i++) {
            const int idx = tid + i * 256;
            const int r  = idx >> 3;
            const int ck = idx & 7;
            const uint32_t so = (uint32_t)(r * 128 + ((ck ^ (r & 7)) << 4));
            const long long ga = (long long)r * lda + kg + ck * 8;
            const long long gb = (long long)r * ldb + kg + ck * 8;
            CP16(bb + AHI_O + so, (const void*)(Abh + ga));
            CP16(bb + ALO_O + so, (const void*)(Abl + ga));
            CP16(bb + BHI_O + so, (const void*)(Bbh + gb));
            CP16(bb + BLO_O + so, (const void*)(Bbl + gb));
        }
        asm volatile("cp.async.commit_group;" ::: "memory");
    };

    load_chunk(0, 0);
    if (NC > 1) load_chunk(1, 1);

    for (int c = 0; c < NC; c++) {
        if (c + 2 < NC) load_chunk(c + 2, (c + 2) % 3);
        const int pend = (NC - 1 - c >= 2) ? 2 : (NC - 1 - c);
        if (pend == 2)      cp_wait<2>();
        else if (pend == 1) cp_wait<1>();
        else                cp_wait<0>();
        __syncthreads();

        const uint32_t ab = sb + (c % 3) * BUFSTRIDE;
#pragma unroll
        for (int ks = 0; ks < 4; ks++) {
            uint32_t ah[2][4], al[2][4], bh[4][4], bl[4][4];
#pragma unroll
            for (int i = 0; i < 2; i++) {
                const int r  = mw * 32 + i * 16 + (lane & 15);
                const int ck = ks * 2 + (lane >> 4);
                const uint32_t off = (uint32_t)(r * 128 + ((ck ^ (r & 7)) << 4));
                ldsm4(ah[i], ab + AHI_O + off);
                ldsm4(al[i], ab + ALO_O + off);
            }
#pragma unroll
            for (int j = 0; j < 4; j++) {
                const int r  = nw * 64 + j * 16 + (lane & 7) + ((lane >> 4) & 1) * 8;
                const int ck = ks * 2 + ((lane >> 3) & 1);
                const uint32_t off = (uint32_t)(r * 128 + ((ck ^ (r & 7)) << 4));
                ldsm4(bh[j], ab + BHI_O + off);
                ldsm4(bl[j], ab + BLO_O + off);
            }
#pragma unroll
            for (int i = 0; i < 2; i++)
#pragma unroll
                for (int f = 0; f < 8; f++) {
                    const uint32_t* Bh = &bh[f >> 1][(f & 1) * 2];
                    const uint32_t* Bl = &bl[f >> 1][(f & 1) * 2];
                    mma16816(acc[i][f], ah[i], Bh);
                    mma16816(acc[i][f], ah[i], Bl);
                    mma16816(acc[i][f], al[i], Bh);
                }
        }
        __syncthreads();
    }

    // Epilogue
#pragma unroll
    for (int i = 0; i < 2; i++) {
#pragma unroll
        for (int hr = 0; hr < 2; hr++) {
            const long long mg = m0 + mw * 32 + i * 16 + hr * 8 + (lane >> 2);
            const int ncol = n0 + nw * 64 + (lane & 3) * 2;
            if (STAGE == 5) {
                float* dst = Cf + mg * ldc + ncol;
#pragma unroll
                for (int f = 0; f < 8; f++) {
                    float2 v;
                    v.x = acc[i][f][hr * 2 + 0];
                    v.y = acc[i][f][hr * 2 + 1];
                    *reinterpret_cast<float2*>(dst + f * 8) = v;
                }
            } else if (STAGE == 3) {
                // E = exp(score) hi/lo, no max subtraction (scores bounded)
                const long long orow = (long long)blockIdx.z * BT * BT + mg * ldc + ncol;
                float part = 0.0f;
#pragma unroll
                for (int f = 0; f < 8; f++) {
                    const float e0 = __expf(acc[i][f][hr * 2 + 0] * alpha);
                    const float e1 = __expf(acc[i][f][hr * 2 + 1] * alpha);
                    part += e0 + e1;
                    __nv_bfloat162 hv, lv;
                    hv.x = __float2bfloat16(e0);
                    hv.y = __float2bfloat16(e1);
                    lv.x = __float2bfloat16(e0 - __bfloat162float(hv.x));
                    lv.y = __float2bfloat16(e1 - __bfloat162float(hv.y));
                    *reinterpret_cast<__nv_bfloat162*>(Chi + orow + f * 8) = hv;
                    *reinterpret_cast<__nv_bfloat162*>(Clo + orow + f * 8) = lv;
                }
                // deterministic per-row reduction: quad shuffle, then cross-warp smem
                part += __shfl_xor_sync(0xffffffffu, part, 1);
                part += __shfl_xor_sync(0xffffffffu, part, 2);
                if ((lane & 3) == 0)
                    srow[nw][mw * 32 + i * 16 + hr * 8 + (lane >> 2)] = part;
            } else if (STAGE == 1) {
                const bool isK = (ncol >= 1024);
                __nv_bfloat16* DH = isK ? Chi2 : Chi;
                __nv_bfloat16* DL = isK ? Clo2 : Clo;
                const long long orow = mg * ldc + (ncol - (isK ? 1024 : 0));
#pragma unroll
                for (int f = 0; f < 8; f++) {
                    const float v0 = acc[i][f][hr * 2 + 0];
                    const float v1 = acc[i][f][hr * 2 + 1];
                    __nv_bfloat162 hv, lv;
                    hv.x = __float2bfloat16(v0);
                    hv.y = __float2bfloat16(v1);
                    lv.x = __float2bfloat16(v0 - __bfloat162float(hv.x));
                    lv.y = __float2bfloat16(v1 - __bfloat162float(hv.y));
                    *reinterpret_cast<__nv_bfloat162*>(DH + orow + f * 8) = hv;
                    *reinterpret_cast<__nv_bfloat162*>(DL + orow + f * 8) = lv;
                }
            } else { // STAGE == 4
                const float rs = Rinv[mg];
                const int b = (int)(mg >> 15);
                const int h = (int)((mg >> 11) & 15);
                const int t = (int)(mg & 2047);
                const long long orow =
                    ((long long)b * BT + t) * ((long long)BHEADS * BDIM) +
                    (long long)h * BDIM + ncol;
#pragma unroll
                for (int f = 0; f < 8; f++) {
                    const float v0 = acc[i][f][hr * 2 + 0] * rs;
                    const float v1 = acc[i][f][hr * 2 + 1] * rs;
                    __nv_bfloat162 hv, lv;
                    hv.x = __float2bfloat16(v0);
                    hv.y = __float2bfloat16(v1);
                    lv.x = __float2bfloat16(v0 - __bfloat162float(hv.x));
                    lv.y = __float2bfloat16(v1 - __bfloat162float(hv.y));
                    *reinterpret_cast<__nv_bfloat162*>(Chi + orow + f * 8) = hv;
                    *reinterpret_cast<__nv_bfloat162*>(Clo + orow + f * 8) = lv;
                }
            }
        }
    }

    if (STAGE == 3) {
        __syncthreads();
        if (tid < HTM) {
            const float s = srow[0][tid] + srow[1][tid];
            Cf[((long long)blockIdx.z * BT + m0 + tid) * 16 + blockIdx.x] = s;
        }
    }
}

// ---------------------------------------------------------------------------
// Launch
// ---------------------------------------------------------------------------
extern "C" void kernel_launch(void* const* d_in, const int* in_sizes, int n_in,
                              void* d_out, int out_size)
{
    const float* x  = (const float*)d_in[0];   // [2,2048,1024]
    const float* Q  = (const float*)d_in[1];   // [16,64,1024]
    const float* K  = (const float*)d_in[2];
    const float* VO = (const float*)d_in[3];   // [16,1024,1024]
    float* out = (float*)d_out;                // [2,2048,1024]

    float *part, *rinv;
    __nv_bfloat16 *phi, *plo, *xhi, *xlo, *qkhi, *qklo;
    __nv_bfloat16 *xqhi, *xqlo, *xkhi, *xklo;
    __nv_bfloat16 *xthi, *xtlo, *ctxhi, *ctxlo, *vothi, *votlo;
    cudaGetSymbolAddress((void**)&part,  g_part);
    cudaGetSymbolAddress((void**)&rinv,  g_rinv);
    cudaGetSymbolAddress((void**)&phi,   g_phi);
    cudaGetSymbolAddress((void**)&plo,   g_plo);
    cudaGetSymbolAddress((void**)&xhi,   g_xhi);
    cudaGetSymbolAddress((void**)&xlo,   g_xlo);
    cudaGetSymbolAddress((void**)&qkhi,  g_qkhi);
    cudaGetSymbolAddress((void**)&qklo,  g_qklo);
    cudaGetSymbolAddress((void**)&xqhi,  g_xqhi);
    cudaGetSymbolAddress((void**)&xqlo,  g_xqlo);
    cudaGetSymbolAddress((void**)&xkhi,  g_xkhi);
    cudaGetSymbolAddress((void**)&xklo,  g_xklo);
    cudaGetSymbolAddress((void**)&xthi,  g_xthi);
    cudaGetSymbolAddress((void**)&xtlo,  g_xtlo);
    cudaGetSymbolAddress((void**)&ctxhi, g_ctxhi);
    cudaGetSymbolAddress((void**)&ctxlo, g_ctxlo);
    cudaGetSymbolAddress((void**)&vothi, g_vothi);
    cudaGetSymbolAddress((void**)&votlo, g_votlo);

    cudaFuncSetAttribute(hmma_gemm<1>, cudaFuncAttributeMaxDynamicSharedMemorySize, HMMA_SMEM);
    cudaFuncSetAttribute(hmma_gemm<3>, cudaFuncAttributeMaxDynamicSharedMemorySize, HMMA_SMEM);
    cudaFuncSetAttribute(hmma_gemm<4>, cudaFuncAttributeMaxDynamicSharedMemorySize, HMMA_SMEM);
    cudaFuncSetAttribute(hmma_gemm<5>, cudaFuncAttributeMaxDynamicSharedMemorySize, HMMA_SMEM);

    const int MBT = BB * BT;                  // 4096
    const int HR  = BHEADS * BRANK;           // 1024
    const int HD  = BHEADS * BDIM;            // 16384

    // Input splits (Q and K stacked into one operand)
    split_f32<<<(MBT * BDIM / 4 + 255) / 256, 256>>>(x, xhi, xlo, (long long)MBT * BDIM / 4);
    split_f32<<<(HR * BDIM / 4 + 255) / 256, 256>>>(Q, qkhi, qklo, (long long)HR * BDIM / 4);
    split_f32<<<(HR * BDIM / 4 + 255) / 256, 256>>>(K, qkhi + (size_t)HR * BDIM,
                                                    qklo + (size_t)HR * BDIM,
                                                    (long long)HR * BDIM / 4);
    transpose_split<<<dim3(BDIM / 32, BT / 32, BB), dim3(32, 8)>>>(
        x, (long long)BT * BDIM, BT, BDIM, xthi, xtlo, BT, (long long)BDIM * BT);
    transpose_split<<<dim3(BDIM / 32, BDIM / 32, BHEADS), dim3(32, 8)>>>(
        VO, (long long)BDIM * BDIM, BDIM, BDIM, vothi, votlo, HD, (long long)BDIM);

    // 1+2) [xq | xk] = x @ [Q;K]^T -> split   M=4096, N=2048, K=1024
    hmma_gemm<1><<<dim3(2 * HR / HTN, MBT / HTM), 256, HMMA_SMEM>>>(
        xhi, xlo, BDIM, qkhi, qklo, BDIM, nullptr,
        xqhi, xqlo, xkhi, xklo, nullptr, HR, BDIM, 1.0f);
    // 3) E = exp(xq @ xk^T / 32) per (b,h) -> hi/lo + partial row sums
    hmma_gemm<3><<<dim3(BT / HTN, BT / HTM, BB * BHEADS), 256, BUFSTRIDE>>>(
        xqhi, xqlo, HR, xkhi, xklo, HR, part,
        phi, plo, nullptr, nullptr, nullptr, BT, BRANK, 0.03125f);
    // 4) reduce partials -> 1/rowsum
    reduce_inv<<<(BB * BHEADS * BT) / 256, 256>>>(part, rinv);
    // 5) ctx = (E @ x) * rinv   M=65536 flat, N=1024, K=2048
    hmma_gemm<4><<<dim3(BDIM / HTN, (BB * BHEADS * BT) / HTM), 256, HMMA_SMEM>>>(
        phi, plo, BT, xthi, xtlo, BT, nullptr,
        ctxhi, ctxlo, nullptr, nullptr, rinv, 0, BT, 1.0f);
    // 6) out = ctx @ VO   M=4096, N=1024, K=16384
    hmma_gemm<5><<<dim3(BDIM / HTN, MBT / HTM), 256, HMMA_SMEM>>>(
        ctxhi, ctxlo, HD, vothi, votlo, HD, out,
        nullptr, nullptr, nullptr, nullptr, nullptr, BDIM, HD, 1.0f);
}